// round 2
// baseline (speedup 1.0000x reference)
#include <cuda_runtime.h>
#include <cstdint>
#include <cstddef>

#define NXD  128
#define TLEN 4096
#define NB   32
#define LCH  64
#define KCH  64
#define NCH  (NB*KCH)     // 2048
#define PD   4096
#define QD   4096

// ---------------- static device workspaces ----------------------------------
__device__ float g_E[NXD*NXD];
__device__ float g_F[NXD*NXD];
__device__ float g_chain[7*NXD*NXD];          // A^(2^s), s=0..6
__device__ float g_Pstack[PD*NXD];            // P_i = C A^i      (4096 x 128)
__device__ float g_PT[NXD*PD];                // P^T              (128 x 4096)
__device__ float g_GBwide[NXD*QD];            // [A^m B] blocks   (128 x 4096)
__device__ float g_Binj[QD*NXD];              // injection op     (4096 x 128)
__device__ float g_Hstack[PD*64];             // H_m = C A^m B    (4096 x 64)
__device__ float g_OmT[(size_t)QD*PD];        // Omega^T          (4096 x 4096)
__device__ float g_V[NCH*NXD];
__device__ float g_X[NCH*NXD];
__device__ float g_Vpart[8*NCH*NXD];

// ---------------- E, F from M ------------------------------------------------
__global__ void ef_kernel(const float* __restrict__ M)
{
    __shared__ float s0i[32][33], s1i[32][33], s0j[32][33], s1j[32][33];
    int tx = threadIdx.x, ty = threadIdx.y;
    int i0 = blockIdx.y * 32, j0 = blockIdx.x * 32;
    float e0 = 0.f, e1 = 0.f, f = 0.f;
    for (int kt = 0; kt < 256; kt += 32) {
        s0i[ty][tx] = M[(i0 + ty) * 256 + kt + tx];
        s1i[ty][tx] = M[(128 + i0 + ty) * 256 + kt + tx];
        s0j[ty][tx] = M[(j0 + ty) * 256 + kt + tx];
        s1j[ty][tx] = M[(128 + j0 + ty) * 256 + kt + tx];
        __syncthreads();
        #pragma unroll
        for (int kk = 0; kk < 32; kk++) {
            float a0 = s0i[ty][kk], a1 = s1i[ty][kk];
            float b0 = s0j[tx][kk], b1 = s1j[tx][kk];
            e0 += a0 * b0; e1 += a1 * b1; f += a1 * b0;
        }
        __syncthreads();
    }
    int i = i0 + ty, j = j0 + tx;
    float e = 0.5f * (e0 + e1);
    if (i == j) e += 1e-9f;
    g_E[i * NXD + j] = e;
    g_F[i * NXD + j] = f;
}

// ---------------- Gauss-Jordan solve E A = F  -> g_chain[0] ------------------
__global__ void solve_kernel()
{
    extern __shared__ float W[];          // 128 x 256 augmented [E|F]
    __shared__ float fs[128];
    int t = threadIdx.x, nt = blockDim.x;
    for (int idx = t; idx < NXD * NXD; idx += nt) {
        int r = idx >> 7, c = idx & 127;
        W[r * 256 + c]       = g_E[idx];
        W[r * 256 + 128 + c] = g_F[idx];
    }
    __syncthreads();
    for (int k = 0; k < 128; k++) {
        if (t < 128) fs[t] = W[t * 256 + k];
        __syncthreads();
        float pinv = 1.0f / fs[k];
        if (t < 256) W[k * 256 + t] *= pinv;
        __syncthreads();
        for (int idx = t; idx < 128 * 256; idx += nt) {
            int r = idx >> 8, c = idx & 255;
            if (r != k) W[r * 256 + c] -= fs[r] * W[k * 256 + c];
        }
        __syncthreads();
    }
    for (int idx = t; idx < NXD * NXD; idx += nt) {
        int r = idx >> 7, c = idx & 127;
        g_chain[idx] = W[r * 256 + 128 + c];
    }
}

// ---------------- generic tiled GEMM C = A*B (row-major) ---------------------
__global__ void mm_nn(float* __restrict__ Cc, const float* __restrict__ A,
                      const float* __restrict__ B,
                      int Mm, int Nn, int Kk, int lda, int ldb, int ldc)
{
    __shared__ float As[16][17], Bs[16][17];
    int tx = threadIdx.x, ty = threadIdx.y;
    int row = blockIdx.y * 16 + ty, col = blockIdx.x * 16 + tx;
    float acc = 0.f;
    for (int k0 = 0; k0 < Kk; k0 += 16) {
        As[ty][tx] = (row < Mm) ? A[row * lda + k0 + tx] : 0.f;
        Bs[ty][tx] = (col < Nn) ? B[(k0 + ty) * ldb + col] : 0.f;
        __syncthreads();
        #pragma unroll
        for (int kk = 0; kk < 16; kk++) acc += As[ty][kk] * Bs[kk][tx];
        __syncthreads();
    }
    if (row < Mm && col < Nn) Cc[row * ldc + col] = acc;
}

// ---------------- small helpers ---------------------------------------------
__global__ void copy_kernel(float* __restrict__ dst, const float* __restrict__ src, int n)
{
    int i = blockIdx.x * blockDim.x + threadIdx.x;
    if (i < n) dst[i] = src[i];
}

__global__ void copy_bmat(const float* __restrict__ Bm)
{
    int i = blockIdx.x * blockDim.x + threadIdx.x;
    if (i < 128 * 64) {
        int r = i >> 6, c = i & 63;
        g_GBwide[r * QD + c] = Bm[i];
    }
}

// Binj[q=(j,uu)][n] = (A^(63-j) B)[n][uu]
__global__ void build_binj()
{
    int q = blockIdx.x, n = threadIdx.x;
    int j = q >> 6, uu = q & 63;
    g_Binj[q * NXD + n] = g_GBwide[n * QD + (63 - j) * 64 + uu];
}

// OmT[q=(j,uu)][p=(i,o)] = (j<i) ? H_{i-1-j}[o][uu] : 0
__global__ void build_omT()
{
    int q = blockIdx.x;
    int j = q >> 6, uu = q & 63;
    size_t base = (size_t)q * PD;
    for (int p = threadIdx.x; p < PD; p += blockDim.x) {
        int i = p >> 6, o = p & 63;
        float v = 0.f;
        if (j < i) v = g_Hstack[(((i - 1 - j) << 6) + o) * 64 + uu];
        g_OmT[base + p] = v;
    }
}

__global__ void transpose_PT()
{
    int p = blockIdx.x * blockDim.x + threadIdx.x;
    int n = blockIdx.y;
    g_PT[n * PD + p] = g_Pstack[p * NXD + n];
}

// ---------------- injection GEMM (split-K=8): Vpart = U_chunks * Binj --------
__global__ void __launch_bounds__(256) gemm_v(const float* __restrict__ U)
{
    __shared__ float As[8][128];
    __shared__ float Bs[8][128];
    int z  = blockIdx.x;
    int rt = blockIdx.y;
    int t  = threadIdx.x;
    int tx = t & 15, ty = t >> 4;
    int lrow = t >> 1, lk = (t & 1) * 4;
    int bkk = t >> 5, bn = (t & 31) * 4;
    int rg = rt * 128 + lrow;
    const float* Arow = U + (size_t)(rg >> 6) * 262144 + (size_t)(rg & 63) * 4096;
    float acc[8][8] = {};
    int kbeg = z * 512, kend = kbeg + 512;
    for (int k0 = kbeg; k0 < kend; k0 += 8) {
        float4 av = *(const float4*)(Arow + k0 + lk);
        As[lk + 0][lrow] = av.x; As[lk + 1][lrow] = av.y;
        As[lk + 2][lrow] = av.z; As[lk + 3][lrow] = av.w;
        *(float4*)&Bs[bkk][bn] = *(const float4*)(g_Binj + (k0 + bkk) * NXD + bn);
        __syncthreads();
        #pragma unroll
        for (int kk = 0; kk < 8; kk++) {
            float a[8], bb[8];
            *(float4*)(a)      = *(float4*)&As[kk][ty * 4];
            *(float4*)(a + 4)  = *(float4*)&As[kk][64 + ty * 4];
            *(float4*)(bb)     = *(float4*)&Bs[kk][tx * 4];
            *(float4*)(bb + 4) = *(float4*)&Bs[kk][64 + tx * 4];
            #pragma unroll
            for (int i = 0; i < 8; i++)
                #pragma unroll
                for (int j = 0; j < 8; j++) acc[i][j] += a[i] * bb[j];
        }
        __syncthreads();
    }
    float* Vp = g_Vpart + (size_t)z * NCH * NXD;
    #pragma unroll
    for (int i = 0; i < 8; i++) {
        int rl = (i < 4) ? (ty * 4 + i) : (64 + ty * 4 + (i - 4));
        int orow = rt * 128 + rl;
        float4 w0 = {acc[i][0], acc[i][1], acc[i][2], acc[i][3]};
        float4 w1 = {acc[i][4], acc[i][5], acc[i][6], acc[i][7]};
        *(float4*)(Vp + orow * NXD + tx * 4)      = w0;
        *(float4*)(Vp + orow * NXD + 64 + tx * 4) = w1;
    }
}

__global__ void reduce_v()
{
    int i = blockIdx.x * blockDim.x + threadIdx.x;
    if (i < NCH * NXD) {
        float s = 0.f;
        #pragma unroll
        for (int z = 0; z < 8; z++) s += g_Vpart[(size_t)z * NCH * NXD + i];
        g_V[i] = s;
    }
}

// ---------------- chunk-level scan: x_{(k+1)L} = A^64 x_{kL} + v_k -----------
__global__ void chunk_scan(const float* __restrict__ x0)
{
    __shared__ float xs[128];
    int b = blockIdx.x, n = threadIdx.x;
    const float* A64 = g_chain + 6 * NXD * NXD;
    xs[n] = x0[n];
    __syncthreads();
    g_X[(b * 64 + 0) * NXD + n] = xs[n];
    for (int k = 0; k < 63; k++) {
        float acc = g_V[(b * 64 + k) * NXD + n];
        #pragma unroll 8
        for (int m = 0; m < 128; m++) acc += A64[n * 128 + m] * xs[m];
        __syncthreads();
        xs[n] = acc;
        __syncthreads();
        g_X[(b * 64 + k + 1) * NXD + n] = acc;
    }
}

// ---------------- main GEMM: Y = Uc*OmT + X*PT, triangular K cutoff ----------
__global__ void __launch_bounds__(256) gemm_main(const float* __restrict__ U,
                                                 float* __restrict__ out)
{
    __shared__ float As[8][128];
    __shared__ float Bs[8][128];
    int ct = blockIdx.x, rt = blockIdx.y;
    int t  = threadIdx.x;
    int tx = t & 15, ty = t >> 4;
    int lrow = t >> 1, lk = (t & 1) * 4;
    int bkk = t >> 5, bn = (t & 31) * 4;
    int rg = rt * 128 + lrow;
    const float* Arow = U + (size_t)(rg >> 6) * 262144 + (size_t)(rg & 63) * 4096;
    int cbase = ct * 128;
    int kend = (2 * ct + 1) * 64;
    float acc[8][8] = {};
    for (int k0 = 0; k0 < kend; k0 += 8) {
        float4 av = *(const float4*)(Arow + k0 + lk);
        As[lk + 0][lrow] = av.x; As[lk + 1][lrow] = av.y;
        As[lk + 2][lrow] = av.z; As[lk + 3][lrow] = av.w;
        *(float4*)&Bs[bkk][bn] =
            *(const float4*)(g_OmT + (size_t)(k0 + bkk) * PD + cbase + bn);
        __syncthreads();
        #pragma unroll
        for (int kk = 0; kk < 8; kk++) {
            float a[8], bb[8];
            *(float4*)(a)      = *(float4*)&As[kk][ty * 4];
            *(float4*)(a + 4)  = *(float4*)&As[kk][64 + ty * 4];
            *(float4*)(bb)     = *(float4*)&Bs[kk][tx * 4];
            *(float4*)(bb + 4) = *(float4*)&Bs[kk][64 + tx * 4];
            #pragma unroll
            for (int i = 0; i < 8; i++)
                #pragma unroll
                for (int j = 0; j < 8; j++) acc[i][j] += a[i] * bb[j];
        }
        __syncthreads();
    }
    // X * P^T contribution (K = 128)
    const float* Xrow = g_X + rg * NXD;
    for (int k0 = 0; k0 < 128; k0 += 8) {
        float4 av = *(const float4*)(Xrow + k0 + lk);
        As[lk + 0][lrow] = av.x; As[lk + 1][lrow] = av.y;
        As[lk + 2][lrow] = av.z; As[lk + 3][lrow] = av.w;
        *(float4*)&Bs[bkk][bn] =
            *(const float4*)(g_PT + (k0 + bkk) * PD + cbase + bn);
        __syncthreads();
        #pragma unroll
        for (int kk = 0; kk < 8; kk++) {
            float a[8], bb[8];
            *(float4*)(a)      = *(float4*)&As[kk][ty * 4];
            *(float4*)(a + 4)  = *(float4*)&As[kk][64 + ty * 4];
            *(float4*)(bb)     = *(float4*)&Bs[kk][tx * 4];
            *(float4*)(bb + 4) = *(float4*)&Bs[kk][64 + tx * 4];
            #pragma unroll
            for (int i = 0; i < 8; i++)
                #pragma unroll
                for (int j = 0; j < 8; j++) acc[i][j] += a[i] * bb[j];
        }
        __syncthreads();
    }
    #pragma unroll
    for (int i = 0; i < 8; i++) {
        int rl = (i < 4) ? (ty * 4 + i) : (64 + ty * 4 + (i - 4));
        int orow = rt * 128 + rl;
        int b = orow >> 6, k = orow & 63;
        float* dst = out + (size_t)b * 262144 + (size_t)k * 4096 + cbase;
        float4 w0 = {acc[i][0], acc[i][1], acc[i][2], acc[i][3]};
        float4 w1 = {acc[i][4], acc[i][5], acc[i][6], acc[i][7]};
        *(float4*)(dst + tx * 4)      = w0;
        *(float4*)(dst + 64 + tx * 4) = w1;
    }
}

// ---------------- host launcher ---------------------------------------------
extern "C" void kernel_launch(void* const* d_in, const int* in_sizes, int n_in,
                              void* d_out, int out_size)
{
    const float* u   = (const float*)d_in[0];
    const float* M   = (const float*)d_in[1];
    const float* Bm  = (const float*)d_in[2];
    const float* C   = (const float*)d_in[3];
    const float* x0  = (const float*)d_in[4];
    float* out = (float*)d_out;

    float *pChain, *pGB, *pP, *pH;
    cudaGetSymbolAddress((void**)&pChain, g_chain);
    cudaGetSymbolAddress((void**)&pGB, g_GBwide);
    cudaGetSymbolAddress((void**)&pP, g_Pstack);
    cudaGetSymbolAddress((void**)&pH, g_Hstack);

    cudaFuncSetAttribute(solve_kernel,
                         cudaFuncAttributeMaxDynamicSharedMemorySize, 131072);

    ef_kernel<<<dim3(4, 4), dim3(32, 32)>>>(M);
    solve_kernel<<<1, 512, 131072>>>();

    // A^(2^s) chain
    for (int s = 0; s < 6; s++)
        mm_nn<<<dim3(8, 8), dim3(16, 16)>>>(pChain + (s + 1) * 16384,
                                            pChain + s * 16384,
                                            pChain + s * 16384,
                                            128, 128, 128, 128, 128, 128);
    // GB blocks by doubling
    copy_bmat<<<32, 256>>>(Bm);
    for (int s = 0; s < 6; s++) {
        int w = 64 << s;
        mm_nn<<<dim3(w / 16, 8), dim3(16, 16)>>>(pGB + w, pChain + s * 16384, pGB,
                                                 128, w, 128, 128, QD, QD);
    }
    // P stack by doubling
    copy_kernel<<<32, 256>>>(pP, C, 64 * 128);
    for (int s = 0; s < 6; s++) {
        int h = 64 << s;
        mm_nn<<<dim3(8, h / 16), dim3(16, 16)>>>(pP + h * 128, pP,
                                                 pChain + s * 16384,
                                                 h, 128, 128, 128, 128, 128);
    }
    // H = P @ B_mat
    mm_nn<<<dim3(4, 256), dim3(16, 16)>>>(pH, pP, Bm, PD, 64, 128, 128, 64, 64);

    build_binj<<<4096, 128>>>();
    build_omT<<<4096, 256>>>();
    transpose_PT<<<dim3(32, 128), 128>>>();

    gemm_v<<<dim3(8, 16), 256>>>(u);
    reduce_v<<<1024, 256>>>();
    chunk_scan<<<32, 128>>>(x0);

    gemm_main<<<dim3(32, 16), 256>>>(u, out);
}

// round 4
// speedup vs baseline: 1.3391x; 1.3391x over previous
#include <cuda_runtime.h>
#include <cstdint>
#include <cstddef>

#define NXD  128
#define TLEN 4096
#define NB   32
#define NCH  (NB*64)      // 2048
#define PD   4096
#define QD   4096

// ---------------- static device workspaces ----------------------------------
__device__ float g_E[NXD*NXD];
__device__ float g_F[NXD*NXD];
__device__ float g_chain[7*NXD*NXD];          // A^(2^s), s=0..6
__device__ float g_Pstack[PD*NXD];            // P_i = C A^i      (4096 x 128) K-major
__device__ float g_GBwide[NXD*QD];            // [A^m B] blocks   (128 x 4096)
__device__ float g_Binj[QD*NXD];              // injection op     (4096 x 128)
__device__ float g_Hstack[PD*64];             // H_m = C A^m B    (4096 x 64)
__device__ float g_Om[(size_t)PD*QD];         // Omega (tf32-rounded) 4096x4096
__device__ float g_Utf[(size_t)NB*TLEN*64];   // tf32-rounded U copy (32MB)
__device__ float g_V[NCH*NXD];
__device__ float g_X[NCH*NXD];                // tf32-rounded chunk states
__device__ float g_Vpart[8*NCH*NXD];

// ---------------- helpers ----------------------------------------------------
__device__ __forceinline__ float to_tf32(float x) {
    uint32_t u;
    asm("cvt.rna.tf32.f32 %0, %1;" : "=r"(u) : "f"(x));
    return __uint_as_float(u);
}
__device__ __forceinline__ uint32_t smem_u32(const void* p) {
    uint32_t a;
    asm("{ .reg .u64 t; cvta.to.shared.u64 t, %1; cvt.u32.u64 %0, t; }"
        : "=r"(a) : "l"(p));
    return a;
}
__device__ __forceinline__ void mma8(float* c, const uint32_t* a, const uint32_t* b) {
    asm volatile(
        "mma.sync.aligned.m16n8k8.row.col.f32.tf32.tf32.f32 "
        "{%0,%1,%2,%3}, {%4,%5,%6,%7}, {%8,%9}, {%0,%1,%2,%3};"
        : "+f"(c[0]), "+f"(c[1]), "+f"(c[2]), "+f"(c[3])
        : "r"(a[0]), "r"(a[1]), "r"(a[2]), "r"(a[3]), "r"(b[0]), "r"(b[1]));
}
__device__ __forceinline__ void cp16(uint32_t dst, const float* src) {
    asm volatile("cp.async.cg.shared.global [%0], [%1], 16;"
                 :: "r"(dst), "l"(src));
}

// ---------------- E, F from M ------------------------------------------------
__global__ void ef_kernel(const float* __restrict__ M)
{
    __shared__ float s0i[32][33], s1i[32][33], s0j[32][33], s1j[32][33];
    int tx = threadIdx.x, ty = threadIdx.y;
    int i0 = blockIdx.y * 32, j0 = blockIdx.x * 32;
    float e0 = 0.f, e1 = 0.f, f = 0.f;
    for (int kt = 0; kt < 256; kt += 32) {
        s0i[ty][tx] = M[(i0 + ty) * 256 + kt + tx];
        s1i[ty][tx] = M[(128 + i0 + ty) * 256 + kt + tx];
        s0j[ty][tx] = M[(j0 + ty) * 256 + kt + tx];
        s1j[ty][tx] = M[(128 + j0 + ty) * 256 + kt + tx];
        __syncthreads();
        #pragma unroll
        for (int kk = 0; kk < 32; kk++) {
            float a0 = s0i[ty][kk], a1 = s1i[ty][kk];
            float b0 = s0j[tx][kk], b1 = s1j[tx][kk];
            e0 += a0 * b0; e1 += a1 * b1; f += a1 * b0;
        }
        __syncthreads();
    }
    int i = i0 + ty, j = j0 + tx;
    float e = 0.5f * (e0 + e1);
    if (i == j) e += 1e-9f;
    g_E[i * NXD + j] = e;
    g_F[i * NXD + j] = f;
}

// ---------------- Gauss-Jordan solve E A = F  -> g_chain[0] ------------------
__global__ void solve_kernel()
{
    extern __shared__ float W[];          // 128 x 256 augmented [E|F]
    __shared__ float fs[128];
    int t = threadIdx.x, nt = blockDim.x;
    for (int idx = t; idx < NXD * NXD; idx += nt) {
        int r = idx >> 7, c = idx & 127;
        W[r * 256 + c]       = g_E[idx];
        W[r * 256 + 128 + c] = g_F[idx];
    }
    __syncthreads();
    for (int k = 0; k < 128; k++) {
        if (t < 128) fs[t] = W[t * 256 + k];
        __syncthreads();
        float pinv = 1.0f / fs[k];
        if (t < 256) W[k * 256 + t] *= pinv;
        __syncthreads();
        for (int idx = t; idx < 128 * 256; idx += nt) {
            int r = idx >> 8, c = idx & 255;
            if (r != k) W[r * 256 + c] -= fs[r] * W[k * 256 + c];
        }
        __syncthreads();
    }
    for (int idx = t; idx < NXD * NXD; idx += nt) {
        int r = idx >> 7, c = idx & 127;
        g_chain[idx] = W[r * 256 + 128 + c];
    }
}

// ---------------- generic tiled GEMM C = A*B (row-major) ---------------------
__global__ void mm_nn(float* __restrict__ Cc, const float* __restrict__ A,
                      const float* __restrict__ B,
                      int Mm, int Nn, int Kk, int lda, int ldb, int ldc)
{
    __shared__ float As[16][17], Bs[16][17];
    int tx = threadIdx.x, ty = threadIdx.y;
    int row = blockIdx.y * 16 + ty, col = blockIdx.x * 16 + tx;
    float acc = 0.f;
    for (int k0 = 0; k0 < Kk; k0 += 16) {
        As[ty][tx] = (row < Mm) ? A[row * lda + k0 + tx] : 0.f;
        Bs[ty][tx] = (col < Nn) ? B[(k0 + ty) * ldb + col] : 0.f;
        __syncthreads();
        #pragma unroll
        for (int kk = 0; kk < 16; kk++) acc += As[ty][kk] * Bs[kk][tx];
        __syncthreads();
    }
    if (row < Mm && col < Nn) Cc[row * ldc + col] = acc;
}

// ---------------- small helpers ---------------------------------------------
__global__ void copy_kernel(float* __restrict__ dst, const float* __restrict__ src, int n)
{
    int i = blockIdx.x * blockDim.x + threadIdx.x;
    if (i < n) dst[i] = src[i];
}

__global__ void copy_bmat(const float* __restrict__ Bm)
{
    int i = blockIdx.x * blockDim.x + threadIdx.x;
    if (i < 128 * 64) {
        int r = i >> 6, c = i & 63;
        g_GBwide[r * QD + c] = Bm[i];
    }
}

__global__ void round_copy_tf32(float* __restrict__ dst, const float* __restrict__ src)
{
    int i = blockIdx.x * blockDim.x + threadIdx.x;
    float4 v = ((const float4*)src)[i];
    v.x = to_tf32(v.x); v.y = to_tf32(v.y);
    v.z = to_tf32(v.z); v.w = to_tf32(v.w);
    ((float4*)dst)[i] = v;
}

__global__ void round_inplace_tf32(float* __restrict__ p)
{
    int i = blockIdx.x * blockDim.x + threadIdx.x;
    float4 v = ((float4*)p)[i];
    v.x = to_tf32(v.x); v.y = to_tf32(v.y);
    v.z = to_tf32(v.z); v.w = to_tf32(v.w);
    ((float4*)p)[i] = v;
}

// Binj[q=(j,uu)][n] = (A^(63-j) B)[n][uu]
__global__ void build_binj()
{
    int q = blockIdx.x, n = threadIdx.x;
    int j = q >> 6, uu = q & 63;
    g_Binj[q * NXD + n] = g_GBwide[n * QD + (63 - j) * 64 + uu];
}

// Om[p=(i,o)][q=(j,uu)] = (j<i) ? H_{i-1-j}[o][uu] : 0   (tf32-rounded)
__global__ void build_om()
{
    int p = blockIdx.x;
    int i = p >> 6, o = p & 63;
    size_t base = (size_t)p * QD;
    for (int q = threadIdx.x; q < QD; q += blockDim.x) {
        int j = q >> 6, uu = q & 63;
        float v = 0.f;
        if (j < i) v = to_tf32(g_Hstack[(((i - 1 - j) << 6) + o) * 64 + uu]);
        g_Om[base + q] = v;
    }
}

// ---------------- injection GEMM (split-K=8): Vpart = U_chunks * Binj --------
__global__ void __launch_bounds__(256) gemm_v(const float* __restrict__ U)
{
    __shared__ float As[8][128];
    __shared__ float Bs[8][128];
    int z  = blockIdx.x;
    int rt = blockIdx.y;
    int t  = threadIdx.x;
    int tx = t & 15, ty = t >> 4;
    int lrow = t >> 1, lk = (t & 1) * 4;
    int bkk = t >> 5, bn = (t & 31) * 4;
    int rg = rt * 128 + lrow;
    const float* Arow = U + (size_t)rg * 4096;
    float acc[8][8] = {};
    int kbeg = z * 512, kend = kbeg + 512;
    for (int k0 = kbeg; k0 < kend; k0 += 8) {
        float4 av = *(const float4*)(Arow + k0 + lk);
        As[lk + 0][lrow] = av.x; As[lk + 1][lrow] = av.y;
        As[lk + 2][lrow] = av.z; As[lk + 3][lrow] = av.w;
        *(float4*)&Bs[bkk][bn] = *(const float4*)(g_Binj + (k0 + bkk) * NXD + bn);
        __syncthreads();
        #pragma unroll
        for (int kk = 0; kk < 8; kk++) {
            float a[8], bb[8];
            *(float4*)(a)      = *(float4*)&As[kk][ty * 4];
            *(float4*)(a + 4)  = *(float4*)&As[kk][64 + ty * 4];
            *(float4*)(bb)     = *(float4*)&Bs[kk][tx * 4];
            *(float4*)(bb + 4) = *(float4*)&Bs[kk][64 + tx * 4];
            #pragma unroll
            for (int i = 0; i < 8; i++)
                #pragma unroll
                for (int j = 0; j < 8; j++) acc[i][j] += a[i] * bb[j];
        }
        __syncthreads();
    }
    float* Vp = g_Vpart + (size_t)z * NCH * NXD;
    #pragma unroll
    for (int i = 0; i < 8; i++) {
        int rl = (i < 4) ? (ty * 4 + i) : (64 + ty * 4 + (i - 4));
        int orow = rt * 128 + rl;
        float4 w0 = {acc[i][0], acc[i][1], acc[i][2], acc[i][3]};
        float4 w1 = {acc[i][4], acc[i][5], acc[i][6], acc[i][7]};
        *(float4*)(Vp + orow * NXD + tx * 4)      = w0;
        *(float4*)(Vp + orow * NXD + 64 + tx * 4) = w1;
    }
}

__global__ void reduce_v()
{
    int i = blockIdx.x * blockDim.x + threadIdx.x;
    if (i < NCH * NXD) {
        float s = 0.f;
        #pragma unroll
        for (int z = 0; z < 8; z++) s += g_Vpart[(size_t)z * NCH * NXD + i];
        g_V[i] = s;
    }
}

// ---------------- chunk-level scan (stores tf32-rounded states) --------------
__global__ void chunk_scan(const float* __restrict__ x0)
{
    __shared__ float xs[128];
    int b = blockIdx.x, n = threadIdx.x;
    const float* A64 = g_chain + 6 * NXD * NXD;
    xs[n] = x0[n];
    __syncthreads();
    g_X[(b * 64 + 0) * NXD + n] = to_tf32(xs[n]);
    for (int k = 0; k < 63; k++) {
        float acc = g_V[(b * 64 + k) * NXD + n];
        #pragma unroll 8
        for (int m = 0; m < 128; m++) acc += A64[n * 128 + m] * xs[m];
        __syncthreads();
        xs[n] = acc;
        __syncthreads();
        g_X[(b * 64 + k + 1) * NXD + n] = to_tf32(acc);
    }
}

// ---------------- main GEMM via mma.sync tf32 --------------------------------
// Y(2048x4096) = Uc * Om^T (triangular K cutoff) + X * P^T
// CTA tile 128x128, 8 warps (2x4), warp tile 64x32, BK=32, cp.async double buf.
#define TSF (128*36)      // padded tile floats per operand

__global__ void __launch_bounds__(256) gemm_main_mma(float* __restrict__ out)
{
    extern __shared__ float sm[];
    int t = threadIdx.x, wid = t >> 5, lane = t & 31;
    int ct = 31 - blockIdx.x;            // LPT: big column tiles first
    int rt = blockIdx.y;

    int mwarp = wid >> 2, nwarp = wid & 3;
    int mbase = mwarp * 64, nbase = nwarp * 32;
    int gr = lane >> 2, gc = lane & 3;

    int kend = (2 * ct + 1) * 64;
    int nU = kend >> 5;
    int NC = nU + 4;

    int frow = t >> 1, fseg = t & 1;     // fill mapping
    const float* AgU = g_Utf + (size_t)(rt * 128 + frow) * 4096 + fseg * 16;
    const float* BgO = g_Om  + (size_t)(ct * 128 + frow) * 4096 + fseg * 16;
    const float* AgX = g_X     + (rt * 128 + frow) * NXD + fseg * 16;
    const float* BgP = g_Pstack + (ct * 128 + frow) * NXD + fseg * 16;

    uint32_t sdA[2], sdB[2];
    #pragma unroll
    for (int b = 0; b < 2; b++) {
        sdA[b] = smem_u32(sm + b * 2 * TSF + frow * 36 + fseg * 16);
        sdB[b] = smem_u32(sm + b * 2 * TSF + TSF + frow * 36 + fseg * 16);
    }

    float acc[4][4][4] = {};

    // issue load for chunk 0
    {
        const float* sa = AgU;
        const float* sb = BgO;
        #pragma unroll
        for (int i = 0; i < 4; i++) { cp16(sdA[0] + i * 16, sa + i * 4);
                                      cp16(sdB[0] + i * 16, sb + i * 4); }
        asm volatile("cp.async.commit_group;");
    }

    for (int ic = 0; ic < NC; ic++) {
        int b = ic & 1;
        if (ic + 1 < NC) {
            int jc = ic + 1, nb = jc & 1;
            const float *sa, *sb;
            if (jc < nU) { sa = AgU + jc * 32; sb = BgO + jc * 32; }
            else { int ko = (jc - nU) * 32; sa = AgX + ko; sb = BgP + ko; }
            #pragma unroll
            for (int i = 0; i < 4; i++) { cp16(sdA[nb] + i * 16, sa + i * 4);
                                          cp16(sdB[nb] + i * 16, sb + i * 4); }
            asm volatile("cp.async.commit_group;");
            asm volatile("cp.async.wait_group 1;");
        } else {
            asm volatile("cp.async.wait_group 0;");
        }
        __syncthreads();

        const float* As = sm + b * 2 * TSF;
        const float* Bs = As + TSF;
        #pragma unroll
        for (int kk = 0; kk < 32; kk += 8) {
            uint32_t af[4][4], bf[4][2];
            #pragma unroll
            for (int mt = 0; mt < 4; mt++) {
                const float* ap = As + (mbase + mt * 16 + gr) * 36 + kk + gc;
                af[mt][0] = __float_as_uint(ap[0]);
                af[mt][1] = __float_as_uint(ap[8 * 36]);
                af[mt][2] = __float_as_uint(ap[4]);
                af[mt][3] = __float_as_uint(ap[8 * 36 + 4]);
            }
            #pragma unroll
            for (int nt = 0; nt < 4; nt++) {
                const float* bp = Bs + (nbase + nt * 8 + gr) * 36 + kk + gc;
                bf[nt][0] = __float_as_uint(bp[0]);
                bf[nt][1] = __float_as_uint(bp[4]);
            }
            #pragma unroll
            for (int mt = 0; mt < 4; mt++)
                #pragma unroll
                for (int nt = 0; nt < 4; nt++)
                    mma8(acc[mt][nt], af[mt], bf[nt]);
        }
        __syncthreads();
    }

    // epilogue
    #pragma unroll
    for (int mt = 0; mt < 4; mt++) {
        int rg0 = rt * 128 + mbase + mt * 16 + gr;
        int rg1 = rg0 + 8;
        float* base0 = out + (size_t)(rg0 >> 6) * 262144 + (size_t)(rg0 & 63) * 4096;
        float* base1 = out + (size_t)(rg1 >> 6) * 262144 + (size_t)(rg1 & 63) * 4096;
        #pragma unroll
        for (int nt = 0; nt < 4; nt++) {
            int p = ct * 128 + nbase + nt * 8 + 2 * gc;
            float2 w0 = {acc[mt][nt][0], acc[mt][nt][1]};
            float2 w1 = {acc[mt][nt][2], acc[mt][nt][3]};
            *(float2*)(base0 + p) = w0;
            *(float2*)(base1 + p) = w1;
        }
    }
}

// ---------------- host launcher ---------------------------------------------
extern "C" void kernel_launch(void* const* d_in, const int* in_sizes, int n_in,
                              void* d_out, int out_size)
{
    const float* u   = (const float*)d_in[0];
    const float* M   = (const float*)d_in[1];
    const float* Bm  = (const float*)d_in[2];
    const float* C   = (const float*)d_in[3];
    const float* x0  = (const float*)d_in[4];
    float* out = (float*)d_out;

    float *pChain, *pGB, *pP, *pH, *pUtf;
    cudaGetSymbolAddress((void**)&pChain, g_chain);
    cudaGetSymbolAddress((void**)&pGB, g_GBwide);
    cudaGetSymbolAddress((void**)&pP, g_Pstack);
    cudaGetSymbolAddress((void**)&pH, g_Hstack);
    cudaGetSymbolAddress((void**)&pUtf, g_Utf);

    cudaFuncSetAttribute(solve_kernel,
                         cudaFuncAttributeMaxDynamicSharedMemorySize, 131072);
    cudaFuncSetAttribute(gemm_main_mma,
                         cudaFuncAttributeMaxDynamicSharedMemorySize, 4 * TSF * 4);

    ef_kernel<<<dim3(4, 4), dim3(32, 32)>>>(M);
    solve_kernel<<<1, 512, 131072>>>();

    // A^(2^s) chain
    for (int s = 0; s < 6; s++)
        mm_nn<<<dim3(8, 8), dim3(16, 16)>>>(pChain + (s + 1) * 16384,
                                            pChain + s * 16384,
                                            pChain + s * 16384,
                                            128, 128, 128, 128, 128, 128);
    // GB blocks by doubling
    copy_bmat<<<32, 256>>>(Bm);
    for (int s = 0; s < 6; s++) {
        int w = 64 << s;
        mm_nn<<<dim3(w / 16, 8), dim3(16, 16)>>>(pGB + w, pChain + s * 16384, pGB,
                                                 128, w, 128, 128, QD, QD);
    }
    // P stack by doubling
    copy_kernel<<<32, 256>>>(pP, C, 64 * 128);
    for (int s = 0; s < 6; s++) {
        int h = 64 << s;
        mm_nn<<<dim3(8, h / 16), dim3(16, 16)>>>(pP + h * 128, pP,
                                                 pChain + s * 16384,
                                                 h, 128, 128, 128, 128, 128);
    }
    // H = P @ B_mat (uses unrounded P), then round P in place for the tail GEMM
    mm_nn<<<dim3(4, 256), dim3(16, 16)>>>(pH, pP, Bm, PD, 64, 128, 128, 64, 64);
    round_inplace_tf32<<<(PD * NXD / 4) / 256, 256>>>(pP);

    build_binj<<<4096, 128>>>();
    build_om<<<4096, 256>>>();
    round_copy_tf32<<<(NB * TLEN * 64 / 4) / 256, 256>>>(pUtf, u);

    gemm_v<<<dim3(8, 16), 256>>>(u);
    reduce_v<<<1024, 256>>>();
    chunk_scan<<<32, 128>>>(x0);

    gemm_main_mma<<<dim3(32, 16), 256, 4 * TSF * 4>>>(out);
}

// round 5
// speedup vs baseline: 1.4795x; 1.1048x over previous
#include <cuda_runtime.h>
#include <cstdint>
#include <cstddef>

#define NXD  128
#define TLEN 4096
#define NB   32
#define NCH  (NB*64)      // 2048
#define PD   4096
#define QD   4096
#define STG_F 8192        // floats per pipeline stage (A 4096 + B 4096)

// ---------------- static device workspaces ----------------------------------
__device__ float g_E[NXD*NXD];
__device__ float g_F[NXD*NXD];
__device__ float g_chain[7*NXD*NXD];          // A^(2^s), s=0..6
__device__ float g_Pstack[PD*NXD];            // P_i = C A^i (raw fp32)
__device__ float g_Ptf[PD*NXD];               // P permuted + tf32
__device__ float g_GBwide[NXD*QD];            // [A^m B] blocks (128 x 4096)
__device__ float g_BinjT[NXD*QD];             // injection op^T, permuted+tf32
__device__ float g_Hstack[PD*64];             // H_m = C A^m B (4096 x 64)
__device__ float g_Om[(size_t)PD*QD];         // Omega, permuted+tf32 (64MB)
__device__ float g_Utf[(size_t)NB*TLEN*64];   // U permuted + tf32 (32MB)
__device__ float g_V[NCH*NXD];
__device__ float g_Xp[NCH*NXD];               // chunk states, permuted+tf32
__device__ float g_Vpart[8*NCH*NXD];

// ---------------- helpers ----------------------------------------------------
__device__ __forceinline__ float to_tf32(float x) {
    uint32_t u;
    asm("cvt.rna.tf32.f32 %0, %1;" : "=r"(u) : "f"(x));
    return __uint_as_float(u);
}
__device__ __forceinline__ uint32_t smem_u32(const void* p) {
    uint32_t a;
    asm("{ .reg .u64 t; cvta.to.shared.u64 t, %1; cvt.u32.u64 %0, t; }"
        : "=r"(a) : "l"(p));
    return a;
}
__device__ __forceinline__ void mma8(float* c, float a0, float a1, float a2,
                                     float a3, float b0, float b1) {
    asm volatile(
        "mma.sync.aligned.m16n8k8.row.col.f32.tf32.tf32.f32 "
        "{%0,%1,%2,%3}, {%4,%5,%6,%7}, {%8,%9}, {%0,%1,%2,%3};"
        : "+f"(c[0]), "+f"(c[1]), "+f"(c[2]), "+f"(c[3])
        : "r"(__float_as_uint(a0)), "r"(__float_as_uint(a1)),
          "r"(__float_as_uint(a2)), "r"(__float_as_uint(a3)),
          "r"(__float_as_uint(b0)), "r"(__float_as_uint(b1)));
}
__device__ __forceinline__ void cp16(uint32_t dst, const float* src) {
    asm volatile("cp.async.cg.shared.global [%0], [%1], 16;"
                 :: "r"(dst), "l"(src));
}
// permutation: source k (within 32-block) stored at pos (k%4)*8 + k/4
__device__ __forceinline__ int kperm(int j) { return ((j & 3) << 3) | (j >> 2); }

// ---------------- E, F from M ------------------------------------------------
__global__ void ef_kernel(const float* __restrict__ M)
{
    __shared__ float s0i[32][33], s1i[32][33], s0j[32][33], s1j[32][33];
    int tx = threadIdx.x, ty = threadIdx.y;
    int i0 = blockIdx.y * 32, j0 = blockIdx.x * 32;
    float e0 = 0.f, e1 = 0.f, f = 0.f;
    for (int kt = 0; kt < 256; kt += 32) {
        s0i[ty][tx] = M[(i0 + ty) * 256 + kt + tx];
        s1i[ty][tx] = M[(128 + i0 + ty) * 256 + kt + tx];
        s0j[ty][tx] = M[(j0 + ty) * 256 + kt + tx];
        s1j[ty][tx] = M[(128 + j0 + ty) * 256 + kt + tx];
        __syncthreads();
        #pragma unroll
        for (int kk = 0; kk < 32; kk++) {
            float a0 = s0i[ty][kk], a1 = s1i[ty][kk];
            float b0 = s0j[tx][kk], b1 = s1j[tx][kk];
            e0 += a0 * b0; e1 += a1 * b1; f += a1 * b0;
        }
        __syncthreads();
    }
    int i = i0 + ty, j = j0 + tx;
    float e = 0.5f * (e0 + e1);
    if (i == j) e += 1e-9f;
    g_E[i * NXD + j] = e;
    g_F[i * NXD + j] = f;
}

// ---------------- Gauss-Jordan solve E A = F  -> g_chain[0] ------------------
__global__ void solve_kernel()
{
    extern __shared__ float W[];          // 128 x 256 augmented [E|F]
    __shared__ float fs[128];
    int t = threadIdx.x, nt = blockDim.x;
    for (int idx = t; idx < NXD * NXD; idx += nt) {
        int r = idx >> 7, c = idx & 127;
        W[r * 256 + c]       = g_E[idx];
        W[r * 256 + 128 + c] = g_F[idx];
    }
    __syncthreads();
    for (int k = 0; k < 128; k++) {
        if (t < 128) fs[t] = W[t * 256 + k];
        __syncthreads();
        float pinv = 1.0f / fs[k];
        if (t < 256) W[k * 256 + t] *= pinv;
        __syncthreads();
        for (int idx = t; idx < 128 * 256; idx += nt) {
            int r = idx >> 8, c = idx & 255;
            if (r != k) W[r * 256 + c] -= fs[r] * W[k * 256 + c];
        }
        __syncthreads();
    }
    for (int idx = t; idx < NXD * NXD; idx += nt) {
        int r = idx >> 7, c = idx & 127;
        g_chain[idx] = W[r * 256 + 128 + c];
    }
}

// ---------------- generic tiled GEMM C = A*B (row-major) for H ---------------
__global__ void mm_nn(float* __restrict__ Cc, const float* __restrict__ A,
                      const float* __restrict__ B,
                      int Mm, int Nn, int Kk, int lda, int ldb, int ldc)
{
    __shared__ float As[16][17], Bs[16][17];
    int tx = threadIdx.x, ty = threadIdx.y;
    int row = blockIdx.y * 16 + ty, col = blockIdx.x * 16 + tx;
    float acc = 0.f;
    for (int k0 = 0; k0 < Kk; k0 += 16) {
        As[ty][tx] = (row < Mm) ? A[row * lda + k0 + tx] : 0.f;
        Bs[ty][tx] = (col < Nn) ? B[(k0 + ty) * ldb + col] : 0.f;
        __syncthreads();
        #pragma unroll
        for (int kk = 0; kk < 16; kk++) acc += As[ty][kk] * Bs[kk][tx];
        __syncthreads();
    }
    if (row < Mm && col < Nn) Cc[row * ldc + col] = acc;
}

// ---------------- fused doubling step: chain^2, GB extend, P extend ----------
__global__ void fused_double(int s)
{
    int w = 64 << s;
    int t1 = w >> 1;                 // GB tiles = 8 * (w/16) = w/2
    int bid = blockIdx.x;
    const float* chain_s = g_chain + s * 16384;
    const float *Ain, *Bin; float* Cout;
    int bx, by, lda, ldb, ldc;
    if (bid < 64) {
        bx = bid & 7; by = bid >> 3;
        Ain = chain_s; Bin = chain_s; Cout = g_chain + (s + 1) * 16384;
        lda = 128; ldb = 128; ldc = 128;
    } else if (bid < 64 + t1) {
        int r = bid - 64; int nt = w >> 4;
        bx = r % nt; by = r / nt;
        Ain = chain_s; Bin = g_GBwide; Cout = g_GBwide + w;
        lda = 128; ldb = 4096; ldc = 4096;
    } else {
        int r = bid - 64 - t1;
        bx = r & 7; by = r >> 3;
        Ain = g_Pstack; Bin = chain_s; Cout = g_Pstack + w * 128;
        lda = 128; ldb = 128; ldc = 128;
    }
    __shared__ float As[16][17], Bs[16][17];
    int tx = threadIdx.x, ty = threadIdx.y;
    int row = by * 16 + ty, col = bx * 16 + tx;
    float acc = 0.f;
    for (int k0 = 0; k0 < 128; k0 += 16) {
        As[ty][tx] = Ain[row * lda + k0 + tx];
        Bs[ty][tx] = Bin[(k0 + ty) * ldb + col];
        __syncthreads();
        #pragma unroll
        for (int kk = 0; kk < 16; kk++) acc += As[ty][kk] * Bs[kk][tx];
        __syncthreads();
    }
    Cout[row * ldc + col] = acc;
}

// ---------------- small helpers ---------------------------------------------
__global__ void copy_kernel(float* __restrict__ dst, const float* __restrict__ src, int n)
{
    int i = blockIdx.x * blockDim.x + threadIdx.x;
    if (i < n) dst[i] = src[i];
}

__global__ void copy_bmat(const float* __restrict__ Bm)
{
    int i = blockIdx.x * blockDim.x + threadIdx.x;
    if (i < 128 * 64) {
        int r = i >> 6, c = i & 63;
        g_GBwide[r * QD + c] = Bm[i];
    }
}

// permute (within 32-k blocks) + tf32 round; cols = 1<<logc
__global__ void permute_tf32(float* __restrict__ dst, const float* __restrict__ src,
                             int n, int logc)
{
    int i = blockIdx.x * blockDim.x + threadIdx.x;
    if (i >= n) return;
    int cmask = (1 << logc) - 1;
    int col = i & cmask;
    int q = col & 31;
    int j = ((q & 7) << 2) | (q >> 3);       // inverse permutation
    dst[i] = to_tf32(src[(i - col) + (col & ~31) + j]);
}

// BinjT[n][perm(q)] = tf32( (A^(63-j) B)[n][uu] ),  q = j*64+uu
__global__ void build_binjT()
{
    int n = blockIdx.x;
    for (int q = threadIdx.x; q < QD; q += blockDim.x) {
        float v = g_GBwide[n * QD + (63 - (q >> 6)) * 64 + (q & 63)];
        g_BinjT[n * QD + (q & ~31) + kperm(q & 31)] = to_tf32(v);
    }
}

// Om[p][perm(q)] = (j<i) ? tf32(H_{i-1-j}[o][uu]) : 0
__global__ void build_om()
{
    int p = blockIdx.x;
    int i = p >> 6, o = p & 63;
    size_t base = (size_t)p * QD;
    for (int q = threadIdx.x; q < QD; q += blockDim.x) {
        int j = q >> 6, uu = q & 63;
        float v = 0.f;
        if (j < i) v = to_tf32(g_Hstack[(((i - 1 - j) << 6) + o) * 64 + uu]);
        g_Om[base + (q & ~31) + kperm(q & 31)] = v;
    }
}

__global__ void reduce_v()
{
    int i = blockIdx.x * blockDim.x + threadIdx.x;
    if (i < NCH * NXD) {
        float s = 0.f;
        #pragma unroll
        for (int z = 0; z < 8; z++) s += g_Vpart[(size_t)z * NCH * NXD + i];
        g_V[i] = s;
    }
}

// ---------------- chunk-level scan (writes permuted tf32 states) -------------
__global__ void chunk_scan(const float* __restrict__ x0)
{
    __shared__ float xs[128];
    int b = blockIdx.x, n = threadIdx.x;
    int np = (n & ~31) | kperm(n & 31);
    const float* A64 = g_chain + 6 * NXD * NXD;
    xs[n] = x0[n];
    __syncthreads();
    g_Xp[(b * 64 + 0) * NXD + np] = to_tf32(xs[n]);
    for (int k = 0; k < 63; k++) {
        float acc = g_V[(b * 64 + k) * NXD + n];
        #pragma unroll 8
        for (int m = 0; m < 128; m++) acc += A64[n * 128 + m] * xs[m];
        __syncthreads();
        xs[n] = acc;
        __syncthreads();
        g_Xp[(b * 64 + k + 1) * NXD + np] = to_tf32(acc);
    }
}

// ---------------- main GEMM via mma.sync tf32, permuted frags ----------------
// Y(2048x4096) = Uc * Om^T (triangular cutoff) + X * P^T
// CTA 128x128, 8 warps (2x4), warp 64x32, BK=32, 3-stage cp.async.
__global__ void __launch_bounds__(256) gemm_main_mma(float* __restrict__ out)
{
    extern __shared__ float sm[];
    int t = threadIdx.x, wid = t >> 5, lane = t & 31;
    int ct = 31 - blockIdx.x, rt = blockIdx.y;
    int mwarp = wid >> 2, nwarp = wid & 3;
    int mbase = mwarp * 64, nbase = nwarp * 32;
    int gr = lane >> 2, gc = lane & 3;

    int kend = (2 * ct + 1) * 64;
    int nU = kend >> 5;
    int NC = nU + 4;

    int fr = t >> 1, fs = t & 1;
    const float* AgU = g_Utf + (size_t)(rt * 128 + fr) * 4096 + fs * 16;
    const float* BgO = g_Om  + (size_t)(ct * 128 + fr) * 4096 + fs * 16;
    const float* AgX = g_Xp  + (rt * 128 + fr) * NXD + fs * 16;
    const float* BgP = g_Ptf + (ct * 128 + fr) * NXD + fs * 16;

    int ubase = (4 * fs) ^ (fr & 7);
    uint32_t dA0 = smem_u32(sm + fr * 32 + ubase * 4);
    uint32_t dB0 = dA0 + 16384;

    auto issue = [&](int jc) {
        const float *sa, *sb;
        if (jc < nU) { sa = AgU + jc * 32; sb = BgO + jc * 32; }
        else { int ko = (jc - nU) * 32; sa = AgX + ko; sb = BgP + ko; }
        uint32_t off = (uint32_t)(jc % 3) * 32768u;
        uint32_t da = dA0 + off, db = dB0 + off;
        #pragma unroll
        for (int i = 0; i < 4; i++) {
            cp16(da ^ (i << 4), sa + i * 4);
            cp16(db ^ (i << 4), sb + i * 4);
        }
        asm volatile("cp.async.commit_group;" ::: "memory");
    };

    float acc[4][4][4] = {};
    int su = (2 * gc) ^ gr;

    issue(0);
    if (NC > 1) issue(1);

    for (int ic = 0; ic < NC; ic++) {
        if (ic + 2 < NC) { issue(ic + 2);
            asm volatile("cp.async.wait_group 2;" ::: "memory"); }
        else if (ic + 1 < NC)
            asm volatile("cp.async.wait_group 1;" ::: "memory");
        else
            asm volatile("cp.async.wait_group 0;" ::: "memory");
        __syncthreads();

        const float4* As4 = (const float4*)(sm + (ic % 3) * STG_F);
        const float4* Bs4 = As4 + 1024;
        #pragma unroll
        for (int h = 0; h < 2; h++) {
            int suh = su ^ h;
            float4 av[4][2], bv[4];
            #pragma unroll
            for (int mt = 0; mt < 4; mt++) {
                av[mt][0] = As4[(mbase + mt * 16 + gr) * 8 + suh];
                av[mt][1] = As4[(mbase + mt * 16 + 8 + gr) * 8 + suh];
            }
            #pragma unroll
            for (int nt = 0; nt < 4; nt++)
                bv[nt] = Bs4[(nbase + nt * 8 + gr) * 8 + suh];
            #pragma unroll
            for (int s2 = 0; s2 < 2; s2++) {
                #pragma unroll
                for (int mt = 0; mt < 4; mt++) {
                    const float* a0p = (const float*)&av[mt][0];
                    const float* a1p = (const float*)&av[mt][1];
                    #pragma unroll
                    for (int nt = 0; nt < 4; nt++) {
                        const float* bp = (const float*)&bv[nt];
                        mma8(acc[mt][nt], a0p[2*s2], a1p[2*s2],
                             a0p[2*s2+1], a1p[2*s2+1], bp[2*s2], bp[2*s2+1]);
                    }
                }
            }
        }
        __syncthreads();
    }

    // epilogue
    #pragma unroll
    for (int mt = 0; mt < 4; mt++) {
        int rg0 = rt * 128 + mbase + mt * 16 + gr;
        int rg1 = rg0 + 8;
        float* base0 = out + (size_t)(rg0 >> 6) * 262144 + (size_t)(rg0 & 63) * 4096;
        float* base1 = out + (size_t)(rg1 >> 6) * 262144 + (size_t)(rg1 & 63) * 4096;
        #pragma unroll
        for (int nt = 0; nt < 4; nt++) {
            int p = ct * 128 + nbase + nt * 8 + 2 * gc;
            float2 w0 = {acc[mt][nt][0], acc[mt][nt][1]};
            float2 w1 = {acc[mt][nt][2], acc[mt][nt][3]};
            *(float2*)(base0 + p) = w0;
            *(float2*)(base1 + p) = w1;
        }
    }
}

// ---------------- injection GEMM via mma (split-K=8) -------------------------
__global__ void __launch_bounds__(256) gemm_v_mma()
{
    extern __shared__ float sm[];
    int t = threadIdx.x, wid = t >> 5, lane = t & 31;
    int z = blockIdx.x, rt = blockIdx.y;
    int mwarp = wid >> 2, nwarp = wid & 3;
    int mbase = mwarp * 64, nbase = nwarp * 32;
    int gr = lane >> 2, gc = lane & 3;
    const int NC = 16;

    int fr = t >> 1, fs = t & 1;
    const float* Ag = g_Utf + (size_t)(rt * 128 + fr) * 4096 + z * 512 + fs * 16;
    const float* Bg = g_BinjT + (size_t)fr * 4096 + z * 512 + fs * 16;

    int ubase = (4 * fs) ^ (fr & 7);
    uint32_t dA0 = smem_u32(sm + fr * 32 + ubase * 4);
    uint32_t dB0 = dA0 + 16384;

    auto issue = [&](int jc) {
        uint32_t off = (uint32_t)(jc % 3) * 32768u;
        uint32_t da = dA0 + off, db = dB0 + off;
        const float* sa = Ag + jc * 32;
        const float* sb = Bg + jc * 32;
        #pragma unroll
        for (int i = 0; i < 4; i++) {
            cp16(da ^ (i << 4), sa + i * 4);
            cp16(db ^ (i << 4), sb + i * 4);
        }
        asm volatile("cp.async.commit_group;" ::: "memory");
    };

    float acc[4][4][4] = {};
    int su = (2 * gc) ^ gr;

    issue(0); issue(1);
    for (int ic = 0; ic < NC; ic++) {
        if (ic + 2 < NC) { issue(ic + 2);
            asm volatile("cp.async.wait_group 2;" ::: "memory"); }
        else if (ic + 1 < NC)
            asm volatile("cp.async.wait_group 1;" ::: "memory");
        else
            asm volatile("cp.async.wait_group 0;" ::: "memory");
        __syncthreads();

        const float4* As4 = (const float4*)(sm + (ic % 3) * STG_F);
        const float4* Bs4 = As4 + 1024;
        #pragma unroll
        for (int h = 0; h < 2; h++) {
            int suh = su ^ h;
            float4 av[4][2], bv[4];
            #pragma unroll
            for (int mt = 0; mt < 4; mt++) {
                av[mt][0] = As4[(mbase + mt * 16 + gr) * 8 + suh];
                av[mt][1] = As4[(mbase + mt * 16 + 8 + gr) * 8 + suh];
            }
            #pragma unroll
            for (int nt = 0; nt < 4; nt++)
                bv[nt] = Bs4[(nbase + nt * 8 + gr) * 8 + suh];
            #pragma unroll
            for (int s2 = 0; s2 < 2; s2++) {
                #pragma unroll
                for (int mt = 0; mt < 4; mt++) {
                    const float* a0p = (const float*)&av[mt][0];
                    const float* a1p = (const float*)&av[mt][1];
                    #pragma unroll
                    for (int nt = 0; nt < 4; nt++) {
                        const float* bp = (const float*)&bv[nt];
                        mma8(acc[mt][nt], a0p[2*s2], a1p[2*s2],
                             a0p[2*s2+1], a1p[2*s2+1], bp[2*s2], bp[2*s2+1]);
                    }
                }
            }
        }
        __syncthreads();
    }

    float* Vp = g_Vpart + (size_t)z * NCH * NXD;
    #pragma unroll
    for (int mt = 0; mt < 4; mt++) {
        int rg0 = rt * 128 + mbase + mt * 16 + gr;
        int rg1 = rg0 + 8;
        #pragma unroll
        for (int nt = 0; nt < 4; nt++) {
            int col = nbase + nt * 8 + 2 * gc;
            float2 w0 = {acc[mt][nt][0], acc[mt][nt][1]};
            float2 w1 = {acc[mt][nt][2], acc[mt][nt][3]};
            *(float2*)(Vp + (size_t)rg0 * NXD + col) = w0;
            *(float2*)(Vp + (size_t)rg1 * NXD + col) = w1;
        }
    }
}

// ---------------- host launcher ---------------------------------------------
extern "C" void kernel_launch(void* const* d_in, const int* in_sizes, int n_in,
                              void* d_out, int out_size)
{
    const float* u   = (const float*)d_in[0];
    const float* M   = (const float*)d_in[1];
    const float* Bm  = (const float*)d_in[2];
    const float* C   = (const float*)d_in[3];
    const float* x0  = (const float*)d_in[4];
    float* out = (float*)d_out;

    float *pP, *pPtf, *pH, *pUtf;
    cudaGetSymbolAddress((void**)&pP, g_Pstack);
    cudaGetSymbolAddress((void**)&pPtf, g_Ptf);
    cudaGetSymbolAddress((void**)&pH, g_Hstack);
    cudaGetSymbolAddress((void**)&pUtf, g_Utf);

    cudaFuncSetAttribute(solve_kernel,
                         cudaFuncAttributeMaxDynamicSharedMemorySize, 131072);
    cudaFuncSetAttribute(gemm_main_mma,
                         cudaFuncAttributeMaxDynamicSharedMemorySize, 98304);
    cudaFuncSetAttribute(gemm_v_mma,
                         cudaFuncAttributeMaxDynamicSharedMemorySize, 98304);

    copy_bmat<<<32, 256>>>(Bm);                 // GB block 0
    copy_kernel<<<32, 256>>>(pP, C, 64 * 128);  // P block 0 = C
    ef_kernel<<<dim3(4, 4), dim3(32, 32)>>>(M);
    solve_kernel<<<1, 512, 131072>>>();

    for (int s = 0; s < 6; s++) {
        int w = 64 << s;
        fused_double<<<64 + w, dim3(16, 16)>>>(s);
    }

    // H = P @ B_mat (raw fp32 P)
    mm_nn<<<dim3(4, 256), dim3(16, 16)>>>(pH, pP, Bm, PD, 64, 128, 128, 64, 64);

    permute_tf32<<<(PD * NXD) / 256, 256>>>(pPtf, pP, PD * NXD, 7);
    build_om<<<4096, 256>>>();
    build_binjT<<<128, 256>>>();
    permute_tf32<<<(NB * TLEN * 64) / 256, 256>>>(pUtf, u, NB * TLEN * 64, 12);

    gemm_v_mma<<<dim3(8, 16), 256, 98304>>>();
    reduce_v<<<1024, 256>>>();
    chunk_scan<<<32, 128>>>(x0);

    gemm_main_mma<<<dim3(32, 16), 256, 98304>>>(out);
}

// round 6
// speedup vs baseline: 1.6961x; 1.1464x over previous
#include <cuda_runtime.h>
#include <cstdint>
#include <cstddef>

#define NXD  128
#define TLEN 4096
#define NB   32
#define NCH  (NB*64)      // 2048
#define PD   4096
#define QD   4096
#define STG_F 8192        // floats per pipeline stage (A 4096 + B 4096)

// ---------------- static device workspaces ----------------------------------
__device__ float g_E[NXD*NXD];
__device__ float g_F[NXD*NXD];
__device__ float g_chain[7*NXD*NXD];          // A^(2^s), s=0..6
__device__ float g_Pstack[PD*NXD];            // P_i = C A^i (raw fp32)
__device__ float g_Ptf[PD*NXD];               // P permuted + tf32
__device__ float g_GBwide[NXD*QD];            // [A^m B] blocks (128 x 4096)
__device__ float g_BinjT[NXD*QD];             // injection op^T, permuted+tf32
__device__ float g_Hstack[PD*64];             // H_m = C A^m B (4096 x 64)
__device__ float g_Om[(size_t)PD*QD];         // Omega, permuted+tf32 (64MB)
__device__ float g_Utf[(size_t)NB*TLEN*64];   // U permuted + tf32 (32MB)
__device__ float g_V[NCH*NXD];
__device__ float g_Xp[NCH*NXD];               // chunk states, permuted+tf32
__device__ float g_Vpart[8*NCH*NXD];

// ---------------- helpers ----------------------------------------------------
__device__ __forceinline__ float to_tf32(float x) {
    uint32_t u;
    asm("cvt.rna.tf32.f32 %0, %1;" : "=r"(u) : "f"(x));
    return __uint_as_float(u);
}
__device__ __forceinline__ uint32_t smem_u32(const void* p) {
    uint32_t a;
    asm("{ .reg .u64 t; cvta.to.shared.u64 t, %1; cvt.u32.u64 %0, t; }"
        : "=r"(a) : "l"(p));
    return a;
}
__device__ __forceinline__ void mma8(float* c, float a0, float a1, float a2,
                                     float a3, float b0, float b1) {
    asm volatile(
        "mma.sync.aligned.m16n8k8.row.col.f32.tf32.tf32.f32 "
        "{%0,%1,%2,%3}, {%4,%5,%6,%7}, {%8,%9}, {%0,%1,%2,%3};"
        : "+f"(c[0]), "+f"(c[1]), "+f"(c[2]), "+f"(c[3])
        : "r"(__float_as_uint(a0)), "r"(__float_as_uint(a1)),
          "r"(__float_as_uint(a2)), "r"(__float_as_uint(a3)),
          "r"(__float_as_uint(b0)), "r"(__float_as_uint(b1)));
}
__device__ __forceinline__ void cp16(uint32_t dst, const float* src) {
    asm volatile("cp.async.cg.shared.global [%0], [%1], 16;"
                 :: "r"(dst), "l"(src));
}
// permutation: source k (within 32-block) stored at pos (k%4)*8 + k/4
__device__ __forceinline__ int kperm(int j) { return ((j & 3) << 3) | (j >> 2); }

// ---------------- E, F from M ------------------------------------------------
__global__ void ef_kernel(const float* __restrict__ M)
{
    __shared__ float s0i[32][33], s1i[32][33], s0j[32][33], s1j[32][33];
    int tx = threadIdx.x, ty = threadIdx.y;
    int i0 = blockIdx.y * 32, j0 = blockIdx.x * 32;
    float e0 = 0.f, e1 = 0.f, f = 0.f;
    for (int kt = 0; kt < 256; kt += 32) {
        s0i[ty][tx] = M[(i0 + ty) * 256 + kt + tx];
        s1i[ty][tx] = M[(128 + i0 + ty) * 256 + kt + tx];
        s0j[ty][tx] = M[(j0 + ty) * 256 + kt + tx];
        s1j[ty][tx] = M[(128 + j0 + ty) * 256 + kt + tx];
        __syncthreads();
        #pragma unroll
        for (int kk = 0; kk < 32; kk++) {
            float a0 = s0i[ty][kk], a1 = s1i[ty][kk];
            float b0 = s0j[tx][kk], b1 = s1j[tx][kk];
            e0 += a0 * b0; e1 += a1 * b1; f += a1 * b0;
        }
        __syncthreads();
    }
    int i = i0 + ty, j = j0 + tx;
    float e = 0.5f * (e0 + e1);
    if (i == j) e += 1e-9f;
    g_E[i * NXD + j] = e;
    g_F[i * NXD + j] = f;
}

// ---------------- register-resident Gauss-Jordan: solve E A = F --------------
// 512 threads: thread (rq = t>>2, cq = t&3) owns cols [cq*64, cq*64+64) of
// the augmented row rq in 16 float4 registers. Per pivot, the pivot row and
// the pivot-quarter column slices bounce through smem.
__global__ void __launch_bounds__(512) solve_kernel()
{
    __shared__ float4 prow4[64];            // pivot row, 256 floats
    __shared__ float  colbuf[128 * 68];     // pivot-quarter dump, padded
    int t = threadIdx.x;
    int rq = t >> 2, cq = t & 3;

    float4 w[16];
    {
        const float* src = (cq < 2) ? (g_E + rq * 128 + cq * 64)
                                    : (g_F + rq * 128 + (cq - 2) * 64);
        #pragma unroll
        for (int i = 0; i < 16; i++) w[i] = ((const float4*)src)[i];
    }
    __syncthreads();

    for (int k = 0; k < 128; k++) {
        int kq = k >> 6;
        if (rq == k) {
            #pragma unroll
            for (int i = 0; i < 16; i++) prow4[cq * 16 + i] = w[i];
        }
        if (cq == kq) {
            float* cb = colbuf + rq * 68;
            #pragma unroll
            for (int i = 0; i < 16; i++) *(float4*)(cb + 4 * i) = w[i];
        }
        __syncthreads();
        float pinv = 1.0f / ((const float*)prow4)[k];
        if (rq == k) {
            #pragma unroll
            for (int i = 0; i < 16; i++) {
                w[i].x *= pinv; w[i].y *= pinv;
                w[i].z *= pinv; w[i].w *= pinv;
            }
        } else {
            float factor = colbuf[rq * 68 + (k & 63)] * pinv;
            #pragma unroll
            for (int i = 0; i < 16; i++) {
                float4 p = prow4[cq * 16 + i];
                w[i].x -= factor * p.x; w[i].y -= factor * p.y;
                w[i].z -= factor * p.z; w[i].w -= factor * p.w;
            }
        }
        __syncthreads();
    }

    if (cq >= 2) {
        float* dst = g_chain + rq * 128 + (cq - 2) * 64;
        #pragma unroll
        for (int i = 0; i < 16; i++) ((float4*)dst)[i] = w[i];
    }
}

// ---------------- generic tiled GEMM C = A*B (row-major) for H ---------------
__global__ void mm_nn(float* __restrict__ Cc, const float* __restrict__ A,
                      const float* __restrict__ B,
                      int Mm, int Nn, int Kk, int lda, int ldb, int ldc)
{
    __shared__ float As[16][17], Bs[16][17];
    int tx = threadIdx.x, ty = threadIdx.y;
    int row = blockIdx.y * 16 + ty, col = blockIdx.x * 16 + tx;
    float acc = 0.f;
    for (int k0 = 0; k0 < Kk; k0 += 16) {
        As[ty][tx] = (row < Mm) ? A[row * lda + k0 + tx] : 0.f;
        Bs[ty][tx] = (col < Nn) ? B[(k0 + ty) * ldb + col] : 0.f;
        __syncthreads();
        #pragma unroll
        for (int kk = 0; kk < 16; kk++) acc += As[ty][kk] * Bs[kk][tx];
        __syncthreads();
    }
    if (row < Mm && col < Nn) Cc[row * ldc + col] = acc;
}

// ---------------- fused doubling step: chain^2, GB extend, P extend ----------
__global__ void fused_double(int s)
{
    int w = 64 << s;
    int t1 = w >> 1;                 // GB tiles = 8 * (w/16) = w/2
    int bid = blockIdx.x;
    const float* chain_s = g_chain + s * 16384;
    const float *Ain, *Bin; float* Cout;
    int bx, by, lda, ldb, ldc;
    if (bid < 64) {
        bx = bid & 7; by = bid >> 3;
        Ain = chain_s; Bin = chain_s; Cout = g_chain + (s + 1) * 16384;
        lda = 128; ldb = 128; ldc = 128;
    } else if (bid < 64 + t1) {
        int r = bid - 64; int nt = w >> 4;
        bx = r % nt; by = r / nt;
        Ain = chain_s; Bin = g_GBwide; Cout = g_GBwide + w;
        lda = 128; ldb = 4096; ldc = 4096;
    } else {
        int r = bid - 64 - t1;
        bx = r & 7; by = r >> 3;
        Ain = g_Pstack; Bin = chain_s; Cout = g_Pstack + w * 128;
        lda = 128; ldb = 128; ldc = 128;
    }
    __shared__ float As[16][17], Bs[16][17];
    int tx = threadIdx.x, ty = threadIdx.y;
    int row = by * 16 + ty, col = bx * 16 + tx;
    float acc = 0.f;
    for (int k0 = 0; k0 < 128; k0 += 16) {
        As[ty][tx] = Ain[row * lda + k0 + tx];
        Bs[ty][tx] = Bin[(k0 + ty) * ldb + col];
        __syncthreads();
        #pragma unroll
        for (int kk = 0; kk < 16; kk++) acc += As[ty][kk] * Bs[kk][tx];
        __syncthreads();
    }
    Cout[row * ldc + col] = acc;
}

// ---------------- small helpers ---------------------------------------------
__global__ void copy_kernel(float* __restrict__ dst, const float* __restrict__ src, int n)
{
    int i = blockIdx.x * blockDim.x + threadIdx.x;
    if (i < n) dst[i] = src[i];
}

__global__ void copy_bmat(const float* __restrict__ Bm)
{
    int i = blockIdx.x * blockDim.x + threadIdx.x;
    if (i < 128 * 64) {
        int r = i >> 6, c = i & 63;
        g_GBwide[r * QD + c] = Bm[i];
    }
}

// permute (within 32-k blocks) + tf32 round; cols = 1<<logc
__global__ void permute_tf32(float* __restrict__ dst, const float* __restrict__ src,
                             int n, int logc)
{
    int i = blockIdx.x * blockDim.x + threadIdx.x;
    if (i >= n) return;
    int cmask = (1 << logc) - 1;
    int col = i & cmask;
    int q = col & 31;
    int j = ((q & 7) << 2) | (q >> 3);       // inverse permutation
    dst[i] = to_tf32(src[(i - col) + (col & ~31) + j]);
}

// BinjT[n][perm(q)] = tf32( (A^(63-j) B)[n][uu] ),  q = j*64+uu
__global__ void build_binjT()
{
    int n = blockIdx.x;
    for (int q = threadIdx.x; q < QD; q += blockDim.x) {
        float v = g_GBwide[n * QD + (63 - (q >> 6)) * 64 + (q & 63)];
        g_BinjT[n * QD + (q & ~31) + kperm(q & 31)] = to_tf32(v);
    }
}

// Om[p][perm(q)] = (j<i) ? tf32(H_{i-1-j}[o][uu]) : 0
__global__ void build_om()
{
    int p = blockIdx.x;
    int i = p >> 6, o = p & 63;
    size_t base = (size_t)p * QD;
    for (int q = threadIdx.x; q < QD; q += blockDim.x) {
        int j = q >> 6, uu = q & 63;
        float v = 0.f;
        if (j < i) v = to_tf32(g_Hstack[(((i - 1 - j) << 6) + o) * 64 + uu]);
        g_Om[base + (q & ~31) + kperm(q & 31)] = v;
    }
}

__global__ void reduce_v()
{
    int i = blockIdx.x * blockDim.x + threadIdx.x;
    if (i < NCH * NXD) {
        float s = 0.f;
        #pragma unroll
        for (int z = 0; z < 8; z++) s += g_Vpart[(size_t)z * NCH * NXD + i];
        g_V[i] = s;
    }
}

// ---------------- chunk-level scan (writes permuted tf32 states) -------------
__global__ void chunk_scan(const float* __restrict__ x0)
{
    __shared__ float xs[128];
    int b = blockIdx.x, n = threadIdx.x;
    int np = (n & ~31) | kperm(n & 31);
    const float* A64 = g_chain + 6 * NXD * NXD;
    xs[n] = x0[n];
    __syncthreads();
    g_Xp[(b * 64 + 0) * NXD + np] = to_tf32(xs[n]);
    for (int k = 0; k < 63; k++) {
        float acc = g_V[(b * 64 + k) * NXD + n];
        #pragma unroll 8
        for (int m = 0; m < 128; m++) acc += A64[n * 128 + m] * xs[m];
        __syncthreads();
        xs[n] = acc;
        __syncthreads();
        g_Xp[(b * 64 + k + 1) * NXD + np] = to_tf32(acc);
    }
}

// ---------------- main GEMM via mma.sync tf32, permuted frags ----------------
// Y(2048x4096) = Uc * Om^T (triangular cutoff) + X * P^T
// CTA 128x128, 8 warps (2x4), warp 64x32, BK=32, 3-stage cp.async.
__global__ void __launch_bounds__(256) gemm_main_mma(float* __restrict__ out)
{
    extern __shared__ float sm[];
    int t = threadIdx.x, wid = t >> 5, lane = t & 31;
    int ct = 31 - blockIdx.x, rt = blockIdx.y;
    int mwarp = wid >> 2, nwarp = wid & 3;
    int mbase = mwarp * 64, nbase = nwarp * 32;
    int gr = lane >> 2, gc = lane & 3;

    int kend = (2 * ct + 1) * 64;
    int nU = kend >> 5;
    int NC = nU + 4;

    int fr = t >> 1, fs = t & 1;
    const float* AgU = g_Utf + (size_t)(rt * 128 + fr) * 4096 + fs * 16;
    const float* BgO = g_Om  + (size_t)(ct * 128 + fr) * 4096 + fs * 16;
    const float* AgX = g_Xp  + (rt * 128 + fr) * NXD + fs * 16;
    const float* BgP = g_Ptf + (ct * 128 + fr) * NXD + fs * 16;

    int ubase = (4 * fs) ^ (fr & 7);
    uint32_t dA0 = smem_u32(sm + fr * 32 + ubase * 4);
    uint32_t dB0 = dA0 + 16384;

    auto issue = [&](int jc) {
        const float *sa, *sb;
        if (jc < nU) { sa = AgU + jc * 32; sb = BgO + jc * 32; }
        else { int ko = (jc - nU) * 32; sa = AgX + ko; sb = BgP + ko; }
        uint32_t off = (uint32_t)(jc % 3) * 32768u;
        uint32_t da = dA0 + off, db = dB0 + off;
        #pragma unroll
        for (int i = 0; i < 4; i++) {
            cp16(da ^ (i << 4), sa + i * 4);
            cp16(db ^ (i << 4), sb + i * 4);
        }
        asm volatile("cp.async.commit_group;" ::: "memory");
    };

    float acc[4][4][4] = {};
    int su = (2 * gc) ^ gr;

    issue(0);
    if (NC > 1) issue(1);

    for (int ic = 0; ic < NC; ic++) {
        if (ic + 2 < NC) { issue(ic + 2);
            asm volatile("cp.async.wait_group 2;" ::: "memory"); }
        else if (ic + 1 < NC)
            asm volatile("cp.async.wait_group 1;" ::: "memory");
        else
            asm volatile("cp.async.wait_group 0;" ::: "memory");
        __syncthreads();

        const float4* As4 = (const float4*)(sm + (ic % 3) * STG_F);
        const float4* Bs4 = As4 + 1024;
        #pragma unroll
        for (int h = 0; h < 2; h++) {
            int suh = su ^ h;
            float4 av[4][2], bv[4];
            #pragma unroll
            for (int mt = 0; mt < 4; mt++) {
                av[mt][0] = As4[(mbase + mt * 16 + gr) * 8 + suh];
                av[mt][1] = As4[(mbase + mt * 16 + 8 + gr) * 8 + suh];
            }
            #pragma unroll
            for (int nt = 0; nt < 4; nt++)
                bv[nt] = Bs4[(nbase + nt * 8 + gr) * 8 + suh];
            #pragma unroll
            for (int s2 = 0; s2 < 2; s2++) {
                #pragma unroll
                for (int mt = 0; mt < 4; mt++) {
                    const float* a0p = (const float*)&av[mt][0];
                    const float* a1p = (const float*)&av[mt][1];
                    #pragma unroll
                    for (int nt = 0; nt < 4; nt++) {
                        const float* bp = (const float*)&bv[nt];
                        mma8(acc[mt][nt], a0p[2*s2], a1p[2*s2],
                             a0p[2*s2+1], a1p[2*s2+1], bp[2*s2], bp[2*s2+1]);
                    }
                }
            }
        }
        __syncthreads();
    }

    // epilogue
    #pragma unroll
    for (int mt = 0; mt < 4; mt++) {
        int rg0 = rt * 128 + mbase + mt * 16 + gr;
        int rg1 = rg0 + 8;
        float* base0 = out + (size_t)(rg0 >> 6) * 262144 + (size_t)(rg0 & 63) * 4096;
        float* base1 = out + (size_t)(rg1 >> 6) * 262144 + (size_t)(rg1 & 63) * 4096;
        #pragma unroll
        for (int nt = 0; nt < 4; nt++) {
            int p = ct * 128 + nbase + nt * 8 + 2 * gc;
            float2 w0 = {acc[mt][nt][0], acc[mt][nt][1]};
            float2 w1 = {acc[mt][nt][2], acc[mt][nt][3]};
            *(float2*)(base0 + p) = w0;
            *(float2*)(base1 + p) = w1;
        }
    }
}

// ---------------- injection GEMM via mma (split-K=8) -------------------------
__global__ void __launch_bounds__(256) gemm_v_mma()
{
    extern __shared__ float sm[];
    int t = threadIdx.x, wid = t >> 5, lane = t & 31;
    int z = blockIdx.x, rt = blockIdx.y;
    int mwarp = wid >> 2, nwarp = wid & 3;
    int mbase = mwarp * 64, nbase = nwarp * 32;
    int gr = lane >> 2, gc = lane & 3;
    const int NC = 16;

    int fr = t >> 1, fs = t & 1;
    const float* Ag = g_Utf + (size_t)(rt * 128 + fr) * 4096 + z * 512 + fs * 16;
    const float* Bg = g_BinjT + (size_t)fr * 4096 + z * 512 + fs * 16;

    int ubase = (4 * fs) ^ (fr & 7);
    uint32_t dA0 = smem_u32(sm + fr * 32 + ubase * 4);
    uint32_t dB0 = dA0 + 16384;

    auto issue = [&](int jc) {
        uint32_t off = (uint32_t)(jc % 3) * 32768u;
        uint32_t da = dA0 + off, db = dB0 + off;
        const float* sa = Ag + jc * 32;
        const float* sb = Bg + jc * 32;
        #pragma unroll
        for (int i = 0; i < 4; i++) {
            cp16(da ^ (i << 4), sa + i * 4);
            cp16(db ^ (i << 4), sb + i * 4);
        }
        asm volatile("cp.async.commit_group;" ::: "memory");
    };

    float acc[4][4][4] = {};
    int su = (2 * gc) ^ gr;

    issue(0); issue(1);
    for (int ic = 0; ic < NC; ic++) {
        if (ic + 2 < NC) { issue(ic + 2);
            asm volatile("cp.async.wait_group 2;" ::: "memory"); }
        else if (ic + 1 < NC)
            asm volatile("cp.async.wait_group 1;" ::: "memory");
        else
            asm volatile("cp.async.wait_group 0;" ::: "memory");
        __syncthreads();

        const float4* As4 = (const float4*)(sm + (ic % 3) * STG_F);
        const float4* Bs4 = As4 + 1024;
        #pragma unroll
        for (int h = 0; h < 2; h++) {
            int suh = su ^ h;
            float4 av[4][2], bv[4];
            #pragma unroll
            for (int mt = 0; mt < 4; mt++) {
                av[mt][0] = As4[(mbase + mt * 16 + gr) * 8 + suh];
                av[mt][1] = As4[(mbase + mt * 16 + 8 + gr) * 8 + suh];
            }
            #pragma unroll
            for (int nt = 0; nt < 4; nt++)
                bv[nt] = Bs4[(nbase + nt * 8 + gr) * 8 + suh];
            #pragma unroll
            for (int s2 = 0; s2 < 2; s2++) {
                #pragma unroll
                for (int mt = 0; mt < 4; mt++) {
                    const float* a0p = (const float*)&av[mt][0];
                    const float* a1p = (const float*)&av[mt][1];
                    #pragma unroll
                    for (int nt = 0; nt < 4; nt++) {
                        const float* bp = (const float*)&bv[nt];
                        mma8(acc[mt][nt], a0p[2*s2], a1p[2*s2],
                             a0p[2*s2+1], a1p[2*s2+1], bp[2*s2], bp[2*s2+1]);
                    }
                }
            }
        }
        __syncthreads();
    }

    float* Vp = g_Vpart + (size_t)z * NCH * NXD;
    #pragma unroll
    for (int mt = 0; mt < 4; mt++) {
        int rg0 = rt * 128 + mbase + mt * 16 + gr;
        int rg1 = rg0 + 8;
        #pragma unroll
        for (int nt = 0; nt < 4; nt++) {
            int col = nbase + nt * 8 + 2 * gc;
            float2 w0 = {acc[mt][nt][0], acc[mt][nt][1]};
            float2 w1 = {acc[mt][nt][2], acc[mt][nt][3]};
            *(float2*)(Vp + (size_t)rg0 * NXD + col) = w0;
            *(float2*)(Vp + (size_t)rg1 * NXD + col) = w1;
        }
    }
}

// ---------------- host launcher ---------------------------------------------
extern "C" void kernel_launch(void* const* d_in, const int* in_sizes, int n_in,
                              void* d_out, int out_size)
{
    const float* u   = (const float*)d_in[0];
    const float* M   = (const float*)d_in[1];
    const float* Bm  = (const float*)d_in[2];
    const float* C   = (const float*)d_in[3];
    const float* x0  = (const float*)d_in[4];
    float* out = (float*)d_out;

    float *pP, *pPtf, *pH, *pUtf;
    cudaGetSymbolAddress((void**)&pP, g_Pstack);
    cudaGetSymbolAddress((void**)&pPtf, g_Ptf);
    cudaGetSymbolAddress((void**)&pH, g_Hstack);
    cudaGetSymbolAddress((void**)&pUtf, g_Utf);

    cudaFuncSetAttribute(gemm_main_mma,
                         cudaFuncAttributeMaxDynamicSharedMemorySize, 98304);
    cudaFuncSetAttribute(gemm_v_mma,
                         cudaFuncAttributeMaxDynamicSharedMemorySize, 98304);

    copy_bmat<<<32, 256>>>(Bm);                 // GB block 0
    copy_kernel<<<32, 256>>>(pP, C, 64 * 128);  // P block 0 = C
    ef_kernel<<<dim3(4, 4), dim3(32, 32)>>>(M);
    solve_kernel<<<1, 512>>>();

    for (int s = 0; s < 6; s++) {
        int w = 64 << s;
        fused_double<<<64 + w, dim3(16, 16)>>>(s);
    }

    // H = P @ B_mat (raw fp32 P)
    mm_nn<<<dim3(4, 256), dim3(16, 16)>>>(pH, pP, Bm, PD, 64, 128, 128, 64, 64);

    permute_tf32<<<(PD * NXD) / 256, 256>>>(pPtf, pP, PD * NXD, 7);
    build_om<<<4096, 256>>>();
    build_binjT<<<128, 256>>>();
    permute_tf32<<<(NB * TLEN * 64) / 256, 256>>>(pUtf, u, NB * TLEN * 64, 12);

    gemm_v_mma<<<dim3(8, 16), 256, 98304>>>();
    reduce_v<<<1024, 256>>>();
    chunk_scan<<<32, 128>>>(x0);

    gemm_main_mma<<<dim3(32, 16), 256, 98304>>>(out);
}

// round 7
// speedup vs baseline: 2.0148x; 1.1879x over previous
#include <cuda_runtime.h>
#include <cstdint>
#include <cstddef>

#define NXD  128
#define TLEN 4096
#define NB   32
#define NCH  (NB*64)      // 2048
#define PD   4096
#define QD   4096
#define STG_F 8192        // floats per pipeline stage (A 4096 + B 4096)

// ---------------- static device workspaces ----------------------------------
__device__ float g_E[NXD*NXD];
__device__ float g_F[NXD*NXD];
__device__ float g_chain[7*NXD*NXD];          // A^(2^s), s=0..6
__device__ float g_Pstack[PD*NXD];            // P_i = C A^i (raw fp32)
__device__ float g_Ptf[PD*NXD];               // P permuted + tf32
__device__ float g_GBwide[NXD*QD];            // [A^m B] blocks (128 x 4096)
__device__ float g_BinjT[NXD*QD];             // injection op^T, permuted+tf32
__device__ float g_Hstack[PD*64];             // H_m = C A^m B (4096 x 64)
__device__ float g_Om[(size_t)PD*QD];         // Omega, permuted+tf32 (64MB)
__device__ float g_Utf[(size_t)NB*TLEN*64];   // U permuted + tf32 (32MB)
__device__ float g_V[NCH*NXD];
__device__ float g_Xp[NCH*NXD];               // chunk states, permuted+tf32
__device__ float g_Vpart[8*NCH*NXD];

// ---------------- helpers ----------------------------------------------------
__device__ __forceinline__ float to_tf32(float x) {
    uint32_t u;
    asm("cvt.rna.tf32.f32 %0, %1;" : "=r"(u) : "f"(x));
    return __uint_as_float(u);
}
__device__ __forceinline__ uint32_t smem_u32(const void* p) {
    uint32_t a;
    asm("{ .reg .u64 t; cvta.to.shared.u64 t, %1; cvt.u32.u64 %0, t; }"
        : "=r"(a) : "l"(p));
    return a;
}
__device__ __forceinline__ void mma8(float* c, float a0, float a1, float a2,
                                     float a3, float b0, float b1) {
    asm volatile(
        "mma.sync.aligned.m16n8k8.row.col.f32.tf32.tf32.f32 "
        "{%0,%1,%2,%3}, {%4,%5,%6,%7}, {%8,%9}, {%0,%1,%2,%3};"
        : "+f"(c[0]), "+f"(c[1]), "+f"(c[2]), "+f"(c[3])
        : "r"(__float_as_uint(a0)), "r"(__float_as_uint(a1)),
          "r"(__float_as_uint(a2)), "r"(__float_as_uint(a3)),
          "r"(__float_as_uint(b0)), "r"(__float_as_uint(b1)));
}
__device__ __forceinline__ void cp16(uint32_t dst, const float* src) {
    asm volatile("cp.async.cg.shared.global [%0], [%1], 16;"
                 :: "r"(dst), "l"(src));
}
// permutation: source k (within 32-block) stored at pos (k%4)*8 + k/4
__device__ __forceinline__ int kperm(int j) { return ((j & 3) << 3) | (j >> 2); }

// ---------------- E, F from M ------------------------------------------------
__global__ void ef_kernel(const float* __restrict__ M)
{
    __shared__ float s0i[32][33], s1i[32][33], s0j[32][33], s1j[32][33];
    int tx = threadIdx.x, ty = threadIdx.y;
    int i0 = blockIdx.y * 32, j0 = blockIdx.x * 32;
    float e0 = 0.f, e1 = 0.f, f = 0.f;
    for (int kt = 0; kt < 256; kt += 32) {
        s0i[ty][tx] = M[(i0 + ty) * 256 + kt + tx];
        s1i[ty][tx] = M[(128 + i0 + ty) * 256 + kt + tx];
        s0j[ty][tx] = M[(j0 + ty) * 256 + kt + tx];
        s1j[ty][tx] = M[(128 + j0 + ty) * 256 + kt + tx];
        __syncthreads();
        #pragma unroll
        for (int kk = 0; kk < 32; kk++) {
            float a0 = s0i[ty][kk], a1 = s1i[ty][kk];
            float b0 = s0j[tx][kk], b1 = s1j[tx][kk];
            e0 += a0 * b0; e1 += a1 * b1; f += a1 * b0;
        }
        __syncthreads();
    }
    int i = i0 + ty, j = j0 + tx;
    float e = 0.5f * (e0 + e1);
    if (i == j) e += 1e-9f;
    g_E[i * NXD + j] = e;
    g_F[i * NXD + j] = f;
}

// ---------------- register-resident Gauss-Jordan: solve E A = F --------------
// 512 threads, warp-grouped quarters: cq = t>>7 (which 64-col quarter of the
// augmented [E|F] row), rq = t&127 (row). One barrier per pivot; pivot row and
// per-row pivot-column scalars double-buffered through smem by parity.
__global__ void __launch_bounds__(512) solve_kernel()
{
    __shared__ float4 prow4[2][64];      // pivot row (unscaled), 256 floats
    __shared__ float  sfac[2][128];      // W[rq][k] per row
    int t = threadIdx.x;
    int cq = t >> 7, rq = t & 127;

    float4 w[16];
    {
        const float* src = (cq < 2) ? (g_E + rq * 128 + cq * 64)
                                    : (g_F + rq * 128 + (cq - 2) * 64);
        #pragma unroll
        for (int i = 0; i < 16; i++) w[i] = ((const float4*)src)[i];
    }

    for (int k = 0; k < 128; k++) {
        int b = k & 1;
        int kq = k >> 6, j = k & 63;
        // owners of the pivot-column quarter publish W[rq][k] (one scalar each)
        if (cq == kq) {
            int jf4 = j >> 2, jc = j & 3;
            float4 v = w[0];
            #pragma unroll
            for (int i = 1; i < 16; i++) if (jf4 == i) v = w[i];
            float f = (jc == 0) ? v.x : (jc == 1) ? v.y
                    : (jc == 2) ? v.z : v.w;
            sfac[b][rq] = f;
        }
        // pivot row publishes its (unscaled) slice
        if (rq == k) {
            #pragma unroll
            for (int i = 0; i < 16; i++) prow4[b][cq * 16 + i] = w[i];
        }
        __syncthreads();

        float pv = sfac[b][k];
        float r;
        asm("rcp.approx.f32 %0, %1;" : "=f"(r) : "f"(pv));
        r = r * (2.0f - pv * r);
        r = r * (2.0f - pv * r);

        if (rq == k) {
            #pragma unroll
            for (int i = 0; i < 16; i++) {
                w[i].x *= r; w[i].y *= r; w[i].z *= r; w[i].w *= r;
            }
        } else {
            float factor = sfac[b][rq] * r;
            #pragma unroll
            for (int i = 0; i < 16; i++) {
                float4 p = prow4[b][cq * 16 + i];
                w[i].x -= factor * p.x; w[i].y -= factor * p.y;
                w[i].z -= factor * p.z; w[i].w -= factor * p.w;
            }
        }
        // next iteration uses the other parity buffers; its writes are
        // separated from this iteration's reads by the next __syncthreads.
    }

    if (cq >= 2) {
        float* dst = g_chain + rq * 128 + (cq - 2) * 64;
        #pragma unroll
        for (int i = 0; i < 16; i++) ((float4*)dst)[i] = w[i];
    }
}

// ---------------- generic tiled GEMM C = A*B (row-major) for H ---------------
__global__ void mm_nn(float* __restrict__ Cc, const float* __restrict__ A,
                      const float* __restrict__ B,
                      int Mm, int Nn, int Kk, int lda, int ldb, int ldc)
{
    __shared__ float As[16][17], Bs[16][17];
    int tx = threadIdx.x, ty = threadIdx.y;
    int row = blockIdx.y * 16 + ty, col = blockIdx.x * 16 + tx;
    float acc = 0.f;
    for (int k0 = 0; k0 < Kk; k0 += 16) {
        As[ty][tx] = (row < Mm) ? A[row * lda + k0 + tx] : 0.f;
        Bs[ty][tx] = (col < Nn) ? B[(k0 + ty) * ldb + col] : 0.f;
        __syncthreads();
        #pragma unroll
        for (int kk = 0; kk < 16; kk++) acc += As[ty][kk] * Bs[kk][tx];
        __syncthreads();
    }
    if (row < Mm && col < Nn) Cc[row * ldc + col] = acc;
}

// ---------------- fused doubling step: chain^2, GB extend, P extend ----------
__global__ void fused_double(int s)
{
    int w = 64 << s;
    int t1 = w >> 1;                 // GB tiles = 8 * (w/16) = w/2
    int bid = blockIdx.x;
    const float* chain_s = g_chain + s * 16384;
    const float *Ain, *Bin; float* Cout;
    int bx, by, lda, ldb, ldc;
    if (bid < 64) {
        bx = bid & 7; by = bid >> 3;
        Ain = chain_s; Bin = chain_s; Cout = g_chain + (s + 1) * 16384;
        lda = 128; ldb = 128; ldc = 128;
    } else if (bid < 64 + t1) {
        int r = bid - 64; int nt = w >> 4;
        bx = r % nt; by = r / nt;
        Ain = chain_s; Bin = g_GBwide; Cout = g_GBwide + w;
        lda = 128; ldb = 4096; ldc = 4096;
    } else {
        int r = bid - 64 - t1;
        bx = r & 7; by = r >> 3;
        Ain = g_Pstack; Bin = chain_s; Cout = g_Pstack + w * 128;
        lda = 128; ldb = 128; ldc = 128;
    }
    __shared__ float As[16][17], Bs[16][17];
    int tx = threadIdx.x, ty = threadIdx.y;
    int row = by * 16 + ty, col = bx * 16 + tx;
    float acc = 0.f;
    for (int k0 = 0; k0 < 128; k0 += 16) {
        As[ty][tx] = Ain[row * lda + k0 + tx];
        Bs[ty][tx] = Bin[(k0 + ty) * ldb + col];
        __syncthreads();
        #pragma unroll
        for (int kk = 0; kk < 16; kk++) acc += As[ty][kk] * Bs[kk][tx];
        __syncthreads();
    }
    Cout[row * ldc + col] = acc;
}

// ---------------- small helpers ---------------------------------------------
__global__ void copy_kernel(float* __restrict__ dst, const float* __restrict__ src, int n)
{
    int i = blockIdx.x * blockDim.x + threadIdx.x;
    if (i < n) dst[i] = src[i];
}

__global__ void copy_bmat(const float* __restrict__ Bm)
{
    int i = blockIdx.x * blockDim.x + threadIdx.x;
    if (i < 128 * 64) {
        int r = i >> 6, c = i & 63;
        g_GBwide[r * QD + c] = Bm[i];
    }
}

// permute (within 32-k blocks) + tf32 round; cols = 1<<logc
__global__ void permute_tf32(float* __restrict__ dst, const float* __restrict__ src,
                             int n, int logc)
{
    int i = blockIdx.x * blockDim.x + threadIdx.x;
    if (i >= n) return;
    int cmask = (1 << logc) - 1;
    int col = i & cmask;
    int q = col & 31;
    int j = ((q & 7) << 2) | (q >> 3);       // inverse permutation
    dst[i] = to_tf32(src[(i - col) + (col & ~31) + j]);
}

// BinjT[n][perm(q)] = tf32( (A^(63-j) B)[n][uu] ),  q = j*64+uu
__global__ void build_binjT()
{
    int n = blockIdx.x;
    for (int q = threadIdx.x; q < QD; q += blockDim.x) {
        float v = g_GBwide[n * QD + (63 - (q >> 6)) * 64 + (q & 63)];
        g_BinjT[n * QD + (q & ~31) + kperm(q & 31)] = to_tf32(v);
    }
}

// Om[p][perm(q)] = (j<i) ? tf32(H_{i-1-j}[o][uu]) : 0
__global__ void build_om()
{
    int p = blockIdx.x;
    int i = p >> 6, o = p & 63;
    size_t base = (size_t)p * QD;
    for (int q = threadIdx.x; q < QD; q += blockDim.x) {
        int j = q >> 6, uu = q & 63;
        float v = 0.f;
        if (j < i) v = to_tf32(g_Hstack[(((i - 1 - j) << 6) + o) * 64 + uu]);
        g_Om[base + (q & ~31) + kperm(q & 31)] = v;
    }
}

__global__ void reduce_v()
{
    int i = blockIdx.x * blockDim.x + threadIdx.x;
    if (i < NCH * NXD) {
        float s = 0.f;
        #pragma unroll
        for (int z = 0; z < 8; z++) s += g_Vpart[(size_t)z * NCH * NXD + i];
        g_V[i] = s;
    }
}

// ---------------- chunk-level scan (writes permuted tf32 states) -------------
__global__ void chunk_scan(const float* __restrict__ x0)
{
    __shared__ float xs[128];
    int b = blockIdx.x, n = threadIdx.x;
    int np = (n & ~31) | kperm(n & 31);
    const float* A64 = g_chain + 6 * NXD * NXD;
    xs[n] = x0[n];
    __syncthreads();
    g_Xp[(b * 64 + 0) * NXD + np] = to_tf32(xs[n]);
    for (int k = 0; k < 63; k++) {
        float acc = g_V[(b * 64 + k) * NXD + n];
        #pragma unroll 8
        for (int m = 0; m < 128; m++) acc += A64[n * 128 + m] * xs[m];
        __syncthreads();
        xs[n] = acc;
        __syncthreads();
        g_Xp[(b * 64 + k + 1) * NXD + np] = to_tf32(acc);
    }
}

// ---------------- main GEMM via mma.sync tf32, permuted frags ----------------
// Y(2048x4096) = Uc * Om^T (triangular cutoff) + X * P^T
// CTA 128x128, 8 warps (2x4), warp 64x32, BK=32, 3-stage cp.async.
__global__ void __launch_bounds__(256) gemm_main_mma(float* __restrict__ out)
{
    extern __shared__ float sm[];
    int t = threadIdx.x, wid = t >> 5, lane = t & 31;
    int ct = 31 - blockIdx.x, rt = blockIdx.y;
    int mwarp = wid >> 2, nwarp = wid & 3;
    int mbase = mwarp * 64, nbase = nwarp * 32;
    int gr = lane >> 2, gc = lane & 3;

    int kend = (2 * ct + 1) * 64;
    int nU = kend >> 5;
    int NC = nU + 4;

    int fr = t >> 1, fs = t & 1;
    const float* AgU = g_Utf + (size_t)(rt * 128 + fr) * 4096 + fs * 16;
    const float* BgO = g_Om  + (size_t)(ct * 128 + fr) * 4096 + fs * 16;
    const float* AgX = g_Xp  + (rt * 128 + fr) * NXD + fs * 16;
    const float* BgP = g_Ptf + (ct * 128 + fr) * NXD + fs * 16;

    int ubase = (4 * fs) ^ (fr & 7);
    uint32_t dA0 = smem_u32(sm + fr * 32 + ubase * 4);
    uint32_t dB0 = dA0 + 16384;

    auto issue = [&](int jc) {
        const float *sa, *sb;
        if (jc < nU) { sa = AgU + jc * 32; sb = BgO + jc * 32; }
        else { int ko = (jc - nU) * 32; sa = AgX + ko; sb = BgP + ko; }
        uint32_t off = (uint32_t)(jc % 3) * 32768u;
        uint32_t da = dA0 + off, db = dB0 + off;
        #pragma unroll
        for (int i = 0; i < 4; i++) {
            cp16(da ^ (i << 4), sa + i * 4);
            cp16(db ^ (i << 4), sb + i * 4);
        }
        asm volatile("cp.async.commit_group;" ::: "memory");
    };

    float acc[4][4][4] = {};
    int su = (2 * gc) ^ gr;

    issue(0);
    if (NC > 1) issue(1);

    for (int ic = 0; ic < NC; ic++) {
        if (ic + 2 < NC) { issue(ic + 2);
            asm volatile("cp.async.wait_group 2;" ::: "memory"); }
        else if (ic + 1 < NC)
            asm volatile("cp.async.wait_group 1;" ::: "memory");
        else
            asm volatile("cp.async.wait_group 0;" ::: "memory");
        __syncthreads();

        const float4* As4 = (const float4*)(sm + (ic % 3) * STG_F);
        const float4* Bs4 = As4 + 1024;
        #pragma unroll
        for (int h = 0; h < 2; h++) {
            int suh = su ^ h;
            float4 av[4][2], bv[4];
            #pragma unroll
            for (int mt = 0; mt < 4; mt++) {
                av[mt][0] = As4[(mbase + mt * 16 + gr) * 8 + suh];
                av[mt][1] = As4[(mbase + mt * 16 + 8 + gr) * 8 + suh];
            }
            #pragma unroll
            for (int nt = 0; nt < 4; nt++)
                bv[nt] = Bs4[(nbase + nt * 8 + gr) * 8 + suh];
            #pragma unroll
            for (int s2 = 0; s2 < 2; s2++) {
                #pragma unroll
                for (int mt = 0; mt < 4; mt++) {
                    const float* a0p = (const float*)&av[mt][0];
                    const float* a1p = (const float*)&av[mt][1];
                    #pragma unroll
                    for (int nt = 0; nt < 4; nt++) {
                        const float* bp = (const float*)&bv[nt];
                        mma8(acc[mt][nt], a0p[2*s2], a1p[2*s2],
                             a0p[2*s2+1], a1p[2*s2+1], bp[2*s2], bp[2*s2+1]);
                    }
                }
            }
        }
        __syncthreads();
    }

    // epilogue
    #pragma unroll
    for (int mt = 0; mt < 4; mt++) {
        int rg0 = rt * 128 + mbase + mt * 16 + gr;
        int rg1 = rg0 + 8;
        float* base0 = out + (size_t)(rg0 >> 6) * 262144 + (size_t)(rg0 & 63) * 4096;
        float* base1 = out + (size_t)(rg1 >> 6) * 262144 + (size_t)(rg1 & 63) * 4096;
        #pragma unroll
        for (int nt = 0; nt < 4; nt++) {
            int p = ct * 128 + nbase + nt * 8 + 2 * gc;
            float2 w0 = {acc[mt][nt][0], acc[mt][nt][1]};
            float2 w1 = {acc[mt][nt][2], acc[mt][nt][3]};
            *(float2*)(base0 + p) = w0;
            *(float2*)(base1 + p) = w1;
        }
    }
}

// ---------------- injection GEMM via mma (split-K=8) -------------------------
__global__ void __launch_bounds__(256) gemm_v_mma()
{
    extern __shared__ float sm[];
    int t = threadIdx.x, wid = t >> 5, lane = t & 31;
    int z = blockIdx.x, rt = blockIdx.y;
    int mwarp = wid >> 2, nwarp = wid & 3;
    int mbase = mwarp * 64, nbase = nwarp * 32;
    int gr = lane >> 2, gc = lane & 3;
    const int NC = 16;

    int fr = t >> 1, fs = t & 1;
    const float* Ag = g_Utf + (size_t)(rt * 128 + fr) * 4096 + z * 512 + fs * 16;
    const float* Bg = g_BinjT + (size_t)fr * 4096 + z * 512 + fs * 16;

    int ubase = (4 * fs) ^ (fr & 7);
    uint32_t dA0 = smem_u32(sm + fr * 32 + ubase * 4);
    uint32_t dB0 = dA0 + 16384;

    auto issue = [&](int jc) {
        uint32_t off = (uint32_t)(jc % 3) * 32768u;
        uint32_t da = dA0 + off, db = dB0 + off;
        const float* sa = Ag + jc * 32;
        const float* sb = Bg + jc * 32;
        #pragma unroll
        for (int i = 0; i < 4; i++) {
            cp16(da ^ (i << 4), sa + i * 4);
            cp16(db ^ (i << 4), sb + i * 4);
        }
        asm volatile("cp.async.commit_group;" ::: "memory");
    };

    float acc[4][4][4] = {};
    int su = (2 * gc) ^ gr;

    issue(0); issue(1);
    for (int ic = 0; ic < NC; ic++) {
        if (ic + 2 < NC) { issue(ic + 2);
            asm volatile("cp.async.wait_group 2;" ::: "memory"); }
        else if (ic + 1 < NC)
            asm volatile("cp.async.wait_group 1;" ::: "memory");
        else
            asm volatile("cp.async.wait_group 0;" ::: "memory");
        __syncthreads();

        const float4* As4 = (const float4*)(sm + (ic % 3) * STG_F);
        const float4* Bs4 = As4 + 1024;
        #pragma unroll
        for (int h = 0; h < 2; h++) {
            int suh = su ^ h;
            float4 av[4][2], bv[4];
            #pragma unroll
            for (int mt = 0; mt < 4; mt++) {
                av[mt][0] = As4[(mbase + mt * 16 + gr) * 8 + suh];
                av[mt][1] = As4[(mbase + mt * 16 + 8 + gr) * 8 + suh];
            }
            #pragma unroll
            for (int nt = 0; nt < 4; nt++)
                bv[nt] = Bs4[(nbase + nt * 8 + gr) * 8 + suh];
            #pragma unroll
            for (int s2 = 0; s2 < 2; s2++) {
                #pragma unroll
                for (int mt = 0; mt < 4; mt++) {
                    const float* a0p = (const float*)&av[mt][0];
                    const float* a1p = (const float*)&av[mt][1];
                    #pragma unroll
                    for (int nt = 0; nt < 4; nt++) {
                        const float* bp = (const float*)&bv[nt];
                        mma8(acc[mt][nt], a0p[2*s2], a1p[2*s2],
                             a0p[2*s2+1], a1p[2*s2+1], bp[2*s2], bp[2*s2+1]);
                    }
                }
            }
        }
        __syncthreads();
    }

    float* Vp = g_Vpart + (size_t)z * NCH * NXD;
    #pragma unroll
    for (int mt = 0; mt < 4; mt++) {
        int rg0 = rt * 128 + mbase + mt * 16 + gr;
        int rg1 = rg0 + 8;
        #pragma unroll
        for (int nt = 0; nt < 4; nt++) {
            int col = nbase + nt * 8 + 2 * gc;
            float2 w0 = {acc[mt][nt][0], acc[mt][nt][1]};
            float2 w1 = {acc[mt][nt][2], acc[mt][nt][3]};
            *(float2*)(Vp + (size_t)rg0 * NXD + col) = w0;
            *(float2*)(Vp + (size_t)rg1 * NXD + col) = w1;
        }
    }
}

// ---------------- host launcher ---------------------------------------------
extern "C" void kernel_launch(void* const* d_in, const int* in_sizes, int n_in,
                              void* d_out, int out_size)
{
    const float* u   = (const float*)d_in[0];
    const float* M   = (const float*)d_in[1];
    const float* Bm  = (const float*)d_in[2];
    const float* C   = (const float*)d_in[3];
    const float* x0  = (const float*)d_in[4];
    float* out = (float*)d_out;

    float *pP, *pPtf, *pH, *pUtf;
    cudaGetSymbolAddress((void**)&pP, g_Pstack);
    cudaGetSymbolAddress((void**)&pPtf, g_Ptf);
    cudaGetSymbolAddress((void**)&pH, g_Hstack);
    cudaGetSymbolAddress((void**)&pUtf, g_Utf);

    cudaFuncSetAttribute(gemm_main_mma,
                         cudaFuncAttributeMaxDynamicSharedMemorySize, 98304);
    cudaFuncSetAttribute(gemm_v_mma,
                         cudaFuncAttributeMaxDynamicSharedMemorySize, 98304);

    copy_bmat<<<32, 256>>>(Bm);                 // GB block 0
    copy_kernel<<<32, 256>>>(pP, C, 64 * 128);  // P block 0 = C
    ef_kernel<<<dim3(4, 4), dim3(32, 32)>>>(M);
    solve_kernel<<<1, 512>>>();

    for (int s = 0; s < 6; s++) {
        int w = 64 << s;
        fused_double<<<64 + w, dim3(16, 16)>>>(s);
    }

    // H = P @ B_mat (raw fp32 P)
    mm_nn<<<dim3(4, 256), dim3(16, 16)>>>(pH, pP, Bm, PD, 64, 128, 128, 64, 64);

    permute_tf32<<<(PD * NXD) / 256, 256>>>(pPtf, pP, PD * NXD, 7);
    build_om<<<4096, 256>>>();
    build_binjT<<<128, 256>>>();
    permute_tf32<<<(NB * TLEN * 64) / 256, 256>>>(pUtf, u, NB * TLEN * 64, 12);

    gemm_v_mma<<<dim3(8, 16), 256, 98304>>>();
    reduce_v<<<1024, 256>>>();
    chunk_scan<<<32, 128>>>(x0);

    gemm_main_mma<<<dim3(32, 16), 256, 98304>>>(out);
}